// round 5
// baseline (speedup 1.0000x reference)
#include <cuda_runtime.h>
#include <cuda_bf16.h>

typedef unsigned int u32;
typedef unsigned long long u64;

// Problem constants
#define BB 4
#define CC 64
#define HH 192
#define WW 192
#define CS (HH*WW)            // channel stride = 36864
#define NT (BB*CC*HH*WW)      // elems per [B,C,H,W] fp32 tensor
#define PT (BB*32*CS)         // elems per packed tensor (uint2 per channel-pair)
#define SP 193                // padded row stride for score matrix in SMEM

// ---------------- static scratch (no runtime allocation allowed) ----------------
__device__ uint2 g_low1p[PT];
__device__ uint2 g_low2p[PT];
__device__ uint2 g_tp[4 * PT];      // packed conv1 outputs, per combo
__device__ uint2 g_ap[4 * PT];      // packed conv2 outputs, per combo
__device__ uint4 g_wp[5][9216];     // prepacked weights: fe1w1,fe2w1,fe1w2,fe2w2,convw
__device__ float g_qk[4 * NT];      // Q1,K1,Q2,K2
__device__ float g_r2l1[NT];
__device__ float g_l2r1[NT];

// ---------------- helpers ----------------
__device__ __forceinline__ void split_pack(float ev, float ov, u32 &hi, u32 &lo)
{
    __nv_bfloat16 eh = __float2bfloat16(ev);
    __nv_bfloat16 oh = __float2bfloat16(ov);
    __nv_bfloat16 el = __float2bfloat16(ev - __bfloat162float(eh));
    __nv_bfloat16 ol = __float2bfloat16(ov - __bfloat162float(oh));
    hi = (u32)__bfloat16_as_ushort(eh) | ((u32)__bfloat16_as_ushort(oh) << 16);
    lo = (u32)__bfloat16_as_ushort(el) | ((u32)__bfloat16_as_ushort(ol) << 16);
}

__device__ __forceinline__ void mma16816(float c[4],
                                         u32 a0, u32 a1, u32 a2, u32 a3,
                                         u32 b0, u32 b1)
{
    asm volatile(
        "mma.sync.aligned.m16n8k16.row.col.f32.bf16.bf16.f32 "
        "{%0,%1,%2,%3}, {%4,%5,%6,%7}, {%8,%9}, {%0,%1,%2,%3};"
        : "+f"(c[0]), "+f"(c[1]), "+f"(c[2]), "+f"(c[3])
        : "r"(a0), "r"(a1), "r"(a2), "r"(a3), "r"(b0), "r"(b1));
}

__device__ __forceinline__ u64 pk2(float lo, float hi)
{
    u64 r;
    asm("mov.b64 %0, {%1,%2};" : "=l"(r) : "f"(lo), "f"(hi));
    return r;
}
__device__ __forceinline__ void upk2(u64 v, float &lo, float &hi)
{
    asm("mov.b64 {%0,%1}, %2;" : "=f"(lo), "=f"(hi) : "l"(v));
}
__device__ __forceinline__ void ffma2(u64 &d, u64 a, u64 b)
{
    asm("fma.rn.f32x2 %0, %1, %2, %0;" : "+l"(d) : "l"(a), "l"(b));
}

// =================================================================================
// Prep kernels (merged: exactly one launch each)
// =================================================================================
__global__ void pack_weights_all(
    const float* __restrict__ w0, const float* __restrict__ w1,
    const float* __restrict__ w2, const float* __restrict__ w3,
    const float* __restrict__ w4, uint4* __restrict__ wp)
{
    int idx = blockIdx.x * 256 + threadIdx.x;
    if (idx >= 5 * 9216) return;
    int which = idx / 9216, r = idx % 9216;
    const float* w = (which == 0) ? w0 : (which == 1) ? w1 :
                     (which == 2) ? w2 : (which == 3) ? w3 : w4;
    int tap = r >> 10, rem = r & 1023;
    int chunk = rem >> 8, rem2 = rem & 255;
    int o = rem2 >> 2, t = rem2 & 3;
    int c2a = chunk * 8 + t, c2b = c2a + 4;
    u32 h0, l0, h1, l1;
    split_pack(__ldg(&w[o * 576 + (2 * c2a) * 9 + tap]),
               __ldg(&w[o * 576 + (2 * c2a + 1) * 9 + tap]), h0, l0);
    split_pack(__ldg(&w[o * 576 + (2 * c2b) * 9 + tap]),
               __ldg(&w[o * 576 + (2 * c2b + 1) * 9 + tap]), h1, l1);
    wp[idx] = make_uint4(h0, h1, l0, l1);
}

__global__ void pack_features_all(const float* __restrict__ x1,
                                  const float* __restrict__ x2,
                                  uint2* __restrict__ xp1,
                                  uint2* __restrict__ xp2)
{
    int gi = blockIdx.x * 256 + threadIdx.x;
    if (gi >= 2 * PT) return;
    const float* x = (gi < PT) ? x1 : x2;
    uint2* xp = (gi < PT) ? xp1 : xp2;
    int i = (gi < PT) ? gi : gi - PT;
    int pos = i % CS;
    int bc2 = i / CS;
    int b = bc2 >> 5, c2 = bc2 & 31;
    const float* p = x + ((b * 64 + 2 * c2) * CS) + pos;
    u32 h, l;
    split_pack(p[0], p[CS], h, l);
    xp[i] = make_uint2(h, l);
}

// =================================================================================
// Tensor-core conv 3x3 (stride1 pad1 C64->C64), bf16x3, prepacked I/O.
// 256 threads = 8 warps; 16x16 pixel tile; warp = 2 image rows x 64 och.
// dy-reuse in two passes: per (chunk,dx) load 5 halo rows of fragments once,
// hi-pass does Ah*Bh + Ah*Bl, lo-pass does Al*Bh (keeps live regs ~100).
// grid (12,12,16): z -> combo = z>>2, b = z&3.
// =================================================================================
#define CONV_SMEM_BYTES (23040*4)

__global__ void __launch_bounds__(256, 2) conv3x3_tc(
    const uint2* __restrict__ xpA, const uint2* __restrict__ xpB, int xstride,
    const uint4* __restrict__ wpA, const uint4* __restrict__ wpB,
    const float* __restrict__ bsA, const float* __restrict__ bsB,
    const float* __restrict__ skA, const float* __restrict__ skB,
    float* __restrict__ yf, uint2* __restrict__ yp, int mode)
{
    extern __shared__ u32 smc[];
    u32* Hhi = smc;
    u32* Hlo = smc + 11520;

    const int bz = blockIdx.z;
    const int combo = bz >> 2, b = bz & 3;
    const uint2* xp = ((combo & 1) ? xpB : xpA) + (size_t)combo * xstride;
    const uint4* wp = (combo >> 1) ? wpB : wpA;
    const float* bias = (combo >> 1) ? bsB : bsA;
    const float* skip = (combo & 1) ? skB : skA;

    const int ty = blockIdx.y, tx = blockIdx.x;
    const int tid = threadIdx.x, wid = tid >> 5, lane = tid & 31;
    const int g = lane >> 2, t = lane & 3;

    // ---- stage packed halo (18x18, zero-padded at image border) ----
    const int y0 = ty * 16 - 1, x0 = tx * 16 - 1;
    for (int i = tid; i < 32 * 18 * 18; i += 256) {
        int c2 = i / 324, r = i % 324;
        int yy = r / 18, xx = r % 18;
        int gy = y0 + yy, gx = x0 + xx;
        uint2 v = make_uint2(0u, 0u);
        if (gy >= 0 && gy < HH && gx >= 0 && gx < WW)
            v = __ldg(&xp[(b * 32 + c2) * CS + gy * WW + gx]);
        Hhi[c2 * 360 + yy * 20 + xx] = v.x;
        Hlo[c2 * 360 + yy * 20 + xx] = v.y;
    }
    __syncthreads();

    float acc[2][8][4];
#pragma unroll
    for (int blk = 0; blk < 2; blk++)
#pragma unroll
        for (int n8 = 0; n8 < 8; n8++)
#pragma unroll
            for (int q = 0; q < 4; q++) acc[blk][n8][q] = 0.f;

    const int row0 = 2 * wid;    // warp's first image row within the tile

    for (int ch = 0; ch < 4; ch++) {
        const int c2b = ch * 8;
#pragma unroll
        for (int dx = 0; dx < 3; dx++) {
            u32 a5[5][4];
            // ---- hi pass: Ah*Bh + Ah*Bl ----
#pragma unroll
            for (int ri = 0; ri < 5; ri++) {
                const int base = (row0 + ri) * 20 + dx;
                const int rA = (c2b + t) * 360 + base;
                const int rB = (c2b + t + 4) * 360 + base;
                a5[ri][0] = Hhi[rA + g];
                a5[ri][1] = Hhi[rA + g + 8];
                a5[ri][2] = Hhi[rB + g];
                a5[ri][3] = Hhi[rB + g + 8];
            }
#pragma unroll
            for (int dy = 0; dy < 3; dy++) {
                const uint4* wrow = wp + (((dy * 3 + dx) * 4 + ch) * 64) * 4 + t;
#pragma unroll
                for (int n8 = 0; n8 < 8; n8++) {
                    uint4 Bv = __ldg(&wrow[(n8 * 8 + g) * 4]);
#pragma unroll
                    for (int blk = 0; blk < 2; blk++) {
                        const int ri = blk + dy;
                        mma16816(acc[blk][n8], a5[ri][0], a5[ri][1], a5[ri][2], a5[ri][3], Bv.x, Bv.y);
                        mma16816(acc[blk][n8], a5[ri][0], a5[ri][1], a5[ri][2], a5[ri][3], Bv.z, Bv.w);
                    }
                }
            }
            // ---- lo pass: Al*Bh ----
#pragma unroll
            for (int ri = 0; ri < 5; ri++) {
                const int base = (row0 + ri) * 20 + dx;
                const int rA = (c2b + t) * 360 + base;
                const int rB = (c2b + t + 4) * 360 + base;
                a5[ri][0] = Hlo[rA + g];
                a5[ri][1] = Hlo[rA + g + 8];
                a5[ri][2] = Hlo[rB + g];
                a5[ri][3] = Hlo[rB + g + 8];
            }
#pragma unroll
            for (int dy = 0; dy < 3; dy++) {
                const uint4* wrow = wp + (((dy * 3 + dx) * 4 + ch) * 64) * 4 + t;
#pragma unroll
                for (int n8 = 0; n8 < 8; n8++) {
                    uint2 Bh = __ldg((const uint2*)&wrow[(n8 * 8 + g) * 4]);
#pragma unroll
                    for (int blk = 0; blk < 2; blk++) {
                        const int ri = blk + dy;
                        mma16816(acc[blk][n8], a5[ri][0], a5[ri][1], a5[ri][2], a5[ri][3], Bh.x, Bh.y);
                    }
                }
            }
        }
    }

    // ---- epilogue ----
    const int gyb = ty * 16 + row0, gxb = tx * 16;
    if (mode == 0) {
        float* yfc = yf + (size_t)combo * NT;
#pragma unroll
        for (int n8 = 0; n8 < 8; n8++) {
#pragma unroll
            for (int blk = 0; blk < 2; blk++) {
                const int gy = gyb + blk;
#pragma unroll
                for (int q = 0; q < 4; q++) {
                    const int och = n8 * 8 + 2 * t + (q & 1);
                    const int px  = gxb + g + ((q >= 2) ? 8 : 0);
                    yfc[((b * 64 + och) * HH + gy) * WW + px] =
                        acc[blk][n8][q] + __ldg(&bias[och]);
                }
            }
        }
    } else {
        uint2* ypc = yp + (size_t)combo * PT;
#pragma unroll
        for (int n8 = 0; n8 < 8; n8++) {
            const int och0 = n8 * 8 + 2 * t;
            const float b0 = __ldg(&bias[och0]);
            const float b1 = __ldg(&bias[och0 + 1]);
            const int c2o = n8 * 4 + t;
#pragma unroll
            for (int blk = 0; blk < 2; blk++) {
                const int gy = gyb + blk;
#pragma unroll
                for (int half = 0; half < 2; half++) {
                    const int px = gxb + g + half * 8;
                    float v0 = acc[blk][n8][half * 2 + 0] + b0;
                    float v1 = acc[blk][n8][half * 2 + 1] + b1;
                    if (mode == 1) {
                        v0 = fmaxf(v0, 0.f);
                        v1 = fmaxf(v1, 0.f);
                    } else {
                        const int off = ((b * 64 + och0) * HH + gy) * WW + px;
                        v0 += __ldg(&skip[off]);
                        v1 += __ldg(&skip[off + CS]);
                    }
                    u32 h, l;
                    split_pack(v0, v1, h, l);
                    ypc[(b * 32 + c2o) * CS + gy * WW + px] = make_uint2(h, l);
                }
            }
        }
    }
}

// =================================================================================
// Fused attention (unchanged, passing): one CTA per (b, h), 256 thr.
// =================================================================================

__device__ __forceinline__ void load_feat(float* fbf, const float* __restrict__ gsrc,
                                          int rb, int tid)
{
#pragma unroll
    for (int k = 0; k < 6; k++) {
        int i4 = tid + k * 256;
        int c2 = i4 / 48, v4 = i4 % 48;
        float4 a4 = *(const float4*)(gsrc + rb + (2 * c2) * CS + v4 * 4);
        float4 b4 = *(const float4*)(gsrc + rb + (2 * c2 + 1) * CS + v4 * 4);
        float4* dst = (float4*)(fbf + (c2 * 192 + v4 * 4) * 2);
        dst[0] = make_float4(a4.x, b4.x, a4.y, b4.y);
        dst[1] = make_float4(a4.z, b4.z, a4.w, b4.w);
    }
}

__device__ __forceinline__ void compute_S(const float* __restrict__ Q, int rb,
                                          const u64* fbu, float* Sb,
                                          int wid, int lane)
{
    const int w0 = wid * 24;
    for (int gg = 0; gg < 6; gg++) {
        const int wr = w0 + gg * 4;
        u64 accp[4][6];
#pragma unroll
        for (int r = 0; r < 4; r++)
#pragma unroll
            for (int j = 0; j < 6; j++) accp[r][j] = 0ull;

        for (int c2 = 0; c2 < 32; c2++) {
            float4 q0 = __ldg((const float4*)(Q + rb + (2 * c2) * CS + wr));
            float4 q1 = __ldg((const float4*)(Q + rb + (2 * c2 + 1) * CS + wr));
            u64 aq0 = pk2(q0.x, q1.x), aq1 = pk2(q0.y, q1.y);
            u64 aq2 = pk2(q0.z, q1.z), aq3 = pk2(q0.w, q1.w);
#pragma unroll
            for (int j = 0; j < 6; j++) {
                u64 kv = fbu[c2 * 192 + lane + 32 * j];
                ffma2(accp[0][j], aq0, kv);
                ffma2(accp[1][j], aq1, kv);
                ffma2(accp[2][j], aq2, kv);
                ffma2(accp[3][j], aq3, kv);
            }
        }
#pragma unroll
        for (int r = 0; r < 4; r++)
#pragma unroll
            for (int j = 0; j < 6; j++) {
                float lo, hi;
                upk2(accp[r][j], lo, hi);
                Sb[(wr + r) * SP + lane + 32 * j] = lo + hi;
            }
    }
}

__device__ __forceinline__ void softmax_rows(float* Sb, int wid, int lane)
{
    for (int r = wid * 24; r < wid * 24 + 24; r++) {
        float v[6];
        float m = -1e30f;
#pragma unroll
        for (int j = 0; j < 6; j++) {
            v[j] = Sb[r * SP + lane + 32 * j];
            m = fmaxf(m, v[j]);
        }
#pragma unroll
        for (int o = 16; o > 0; o >>= 1)
            m = fmaxf(m, __shfl_xor_sync(0xffffffffu, m, o));
        float s = 0.f;
#pragma unroll
        for (int j = 0; j < 6; j++) { v[j] = __expf(v[j] - m); s += v[j]; }
#pragma unroll
        for (int o = 16; o > 0; o >>= 1)
            s += __shfl_xor_sync(0xffffffffu, s, o);
        float inv = 1.0f / s;
#pragma unroll
        for (int j = 0; j < 6; j++)
            Sb[r * SP + lane + 32 * j] = v[j] * inv;
    }
}

template <bool TRANSP>
__device__ __forceinline__ void apply_gemm(const u64* fbu, const float* Sb,
                                           float t[48], int wid, int lane)
{
    u64 acc2[4][6];
#pragma unroll
    for (int ci2 = 0; ci2 < 4; ci2++)
#pragma unroll
        for (int j = 0; j < 6; j++) acc2[ci2][j] = 0ull;

    const int fbase = wid * 4 * 192;
    for (int v = 0; v < 192; v += 4) {
        u64 fp[4][4];
#pragma unroll
        for (int ci2 = 0; ci2 < 4; ci2++) {
            ulonglong2 u0 = *(const ulonglong2*)(fbu + fbase + ci2 * 192 + v);
            ulonglong2 u1 = *(const ulonglong2*)(fbu + fbase + ci2 * 192 + v + 2);
            fp[ci2][0] = u0.x; fp[ci2][1] = u0.y;
            fp[ci2][2] = u1.x; fp[ci2][3] = u1.y;
        }
#pragma unroll
        for (int dv = 0; dv < 4; dv++) {
#pragma unroll
            for (int j = 0; j < 6; j++) {
                float s = TRANSP ? Sb[(v + dv) * SP + lane + 32 * j]
                                 : Sb[(lane + 32 * j) * SP + (v + dv)];
                u64 s2 = pk2(s, s);
                ffma2(acc2[0][j], fp[0][dv], s2);
                ffma2(acc2[1][j], fp[1][dv], s2);
                ffma2(acc2[2][j], fp[2][dv], s2);
                ffma2(acc2[3][j], fp[3][dv], s2);
            }
        }
    }
#pragma unroll
    for (int ci2 = 0; ci2 < 4; ci2++)
#pragma unroll
        for (int j = 0; j < 6; j++) {
            float lo, hi;
            upk2(acc2[ci2][j], lo, hi);
            t[(2 * ci2) * 6 + j] = lo;
            t[(2 * ci2 + 1) * 6 + j] = hi;
        }
}

__device__ __forceinline__ void emit_init(float* dst, float* scratch,
                                          const float* base, const float t[48],
                                          int rb, int wid, int lane)
{
    const int c0 = wid * 8;
#pragma unroll
    for (int ci = 0; ci < 8; ci++)
#pragma unroll
        for (int j = 0; j < 6; j++) {
            int off = rb + (c0 + ci) * CS + lane + 32 * j;
            float v = t[ci * 6 + j];
            scratch[off] = v;
            dst[off] = base[off] + v;
        }
}

__device__ __forceinline__ void emit_add(float* dst, const float t[48],
                                         int rb, int wid, int lane)
{
    const int c0 = wid * 8;
#pragma unroll
    for (int ci = 0; ci < 8; ci++)
#pragma unroll
        for (int j = 0; j < 6; j++) {
            int off = rb + (c0 + ci) * CS + lane + 32 * j;
            dst[off] += t[ci * 6 + j];
        }
}

__global__ void __launch_bounds__(256, 1) attn_kernel(
    const float* __restrict__ low1, const float* __restrict__ low2,
    const float* __restrict__ Q1, const float* __restrict__ K1,
    const float* __restrict__ Q2, const float* __restrict__ K2,
    float* __restrict__ r2l1s, float* __restrict__ l2r1s,
    float* __restrict__ outL, float* __restrict__ outR)
{
    extern __shared__ float smf[];
    float* Sb  = smf;
    float* fbf = smf + 192 * SP;
    const u64* fbu = (const u64*)fbf;

    const int h = blockIdx.x, b = blockIdx.y;
    const int tid = threadIdx.x, wid = tid >> 5, lane = tid & 31;
    const int rb = b * 64 * CS + h * WW;
    float t[48];

    load_feat(fbf, K1, rb, tid); __syncthreads();
    compute_S(Q1, rb, fbu, Sb, wid, lane); __syncthreads();
    softmax_rows(Sb, wid, lane); __syncthreads();

    load_feat(fbf, low2, rb, tid); __syncthreads();
    apply_gemm<false>(fbu, Sb, t, wid, lane);
    emit_init(outL, r2l1s, low1, t, rb, wid, lane);
    __syncthreads();

    load_feat(fbf, low1, rb, tid); __syncthreads();
    apply_gemm<true>(fbu, Sb, t, wid, lane);
    emit_init(outR, l2r1s, low2, t, rb, wid, lane);
    __syncthreads();

    load_feat(fbf, K2, rb, tid); __syncthreads();
    compute_S(Q2, rb, fbu, Sb, wid, lane); __syncthreads();
    softmax_rows(Sb, wid, lane); __syncthreads();

    load_feat(fbf, low2, rb, tid); __syncthreads();
    apply_gemm<false>(fbu, Sb, t, wid, lane);
    emit_add(outL, t, rb, wid, lane); __syncthreads();

    load_feat(fbf, low1, rb, tid); __syncthreads();
    apply_gemm<true>(fbu, Sb, t, wid, lane);
    emit_add(outR, t, rb, wid, lane); __syncthreads();

    load_feat(fbf, l2r1s, rb, tid); __syncthreads();
    apply_gemm<false>(fbu, Sb, t, wid, lane);
    emit_add(outL, t, rb, wid, lane); __syncthreads();

    load_feat(fbf, r2l1s, rb, tid); __syncthreads();
    apply_gemm<true>(fbu, Sb, t, wid, lane);
    emit_add(outR, t, rb, wid, lane);
}

// =================================================================================
extern "C" void kernel_launch(void* const* d_in, const int* in_sizes, int n_in,
                              void* d_out, int out_size)
{
    const float* low1   = (const float*)d_in[0];
    const float* low2   = (const float*)d_in[1];
    const float* fe1_w1 = (const float*)d_in[2];
    const float* fe1_b1 = (const float*)d_in[3];
    const float* fe1_w2 = (const float*)d_in[4];
    const float* fe1_b2 = (const float*)d_in[5];
    const float* fe2_w1 = (const float*)d_in[6];
    const float* fe2_b1 = (const float*)d_in[7];
    const float* fe2_w2 = (const float*)d_in[8];
    const float* fe2_b2 = (const float*)d_in[9];
    const float* conv_w = (const float*)d_in[10];
    const float* conv_b = (const float*)d_in[11];
    float* out = (float*)d_out;

    uint2 *low1p, *low2p, *tp, *ap;
    uint4 *wp;
    float *qk, *r2l1, *l2r1;
    cudaGetSymbolAddress((void**)&low1p, g_low1p);
    cudaGetSymbolAddress((void**)&low2p, g_low2p);
    cudaGetSymbolAddress((void**)&tp,    g_tp);
    cudaGetSymbolAddress((void**)&ap,    g_ap);
    cudaGetSymbolAddress((void**)&wp,    g_wp);
    cudaGetSymbolAddress((void**)&qk,    g_qk);
    cudaGetSymbolAddress((void**)&r2l1,  g_r2l1);
    cudaGetSymbolAddress((void**)&l2r1,  g_l2r1);

    // pack order: fe1w1, fe2w1, fe1w2, fe2w2, convw
    uint4* wp_fe1w1 = wp + 0 * 9216;
    uint4* wp_fe2w1 = wp + 1 * 9216;
    uint4* wp_fe1w2 = wp + 2 * 9216;
    uint4* wp_fe2w2 = wp + 3 * 9216;
    uint4* wp_convw = wp + 4 * 9216;

    cudaFuncSetAttribute(conv3x3_tc,
                         cudaFuncAttributeMaxDynamicSharedMemorySize,
                         CONV_SMEM_BYTES);
    const int attn_smem = (192 * SP + 2 * 32 * 192) * (int)sizeof(float); // 197376
    cudaFuncSetAttribute(attn_kernel,
                         cudaFuncAttributeMaxDynamicSharedMemorySize, attn_smem);

    const dim3 cgrid(WW / 16, HH / 16, 4 * BB);

    // launch 0: all weight packing in one kernel
    pack_weights_all<<<180, 256>>>(fe1_w1, fe2_w1, fe1_w2, fe2_w2, conv_w, wp);
    // launch 1: both feature packs in one kernel
    pack_features_all<<<(2 * PT + 255) / 256, 256>>>(low1, low2, low1p, low2p);

    // launch 2: conv stage 1: t[combo] = relu(conv(low, w1) + b1)   (packed out)
    conv3x3_tc<<<cgrid, 256, CONV_SMEM_BYTES>>>(
        low1p, low2p, 0, wp_fe1w1, wp_fe2w1, fe1_b1, fe2_b1,
        nullptr, nullptr, nullptr, tp, 1);
    // launch 3: conv stage 2: a[combo] = low + conv(t, w2) + b2     (packed out)
    conv3x3_tc<<<cgrid, 256, CONV_SMEM_BYTES>>>(
        tp, tp, PT, wp_fe1w2, wp_fe2w2, fe1_b2, fe2_b2,
        low1, low2, nullptr, ap, 2);
    // launch 4: conv stage 3: qk[combo] = conv(a, conv_w) + conv_b  (fp32 out)
    conv3x3_tc<<<cgrid, 256, CONV_SMEM_BYTES>>>(
        ap, ap, PT, wp_convw, wp_convw, conv_b, conv_b,
        nullptr, nullptr, qk, nullptr, 0);

    // launch 5: attention
    attn_kernel<<<dim3(HH, BB), 256, attn_smem>>>(
        low1, low2, qk, qk + NT, qk + 2 * NT, qk + 3 * NT,
        r2l1, l2r1, out, out + NT);
}

// round 6
// speedup vs baseline: 1.2897x; 1.2897x over previous
#include <cuda_runtime.h>
#include <cuda_bf16.h>

typedef unsigned int u32;
typedef unsigned long long u64;

// Problem constants
#define BB 4
#define CC 64
#define HH 192
#define WW 192
#define CS (HH*WW)            // channel stride = 36864
#define NT (BB*CC*HH*WW)      // elems per [B,C,H,W] fp32 tensor
#define NPIX (BB*HH*WW)       // pixels per tensor = 147456
#define SP 193                // padded row stride for score matrix in SMEM

// ---------------- static scratch (no runtime allocation allowed) ----------------
// NHWC packed feature format: per pixel 16 uint4; uint4 j = {hi(c2=2j), lo(2j),
// hi(2j+1), lo(2j+1)} where c2 pair = channels (2c2, 2c2+1), hi/lo = bf16x2 split.
__device__ uint4 g_low1p[NPIX * 16];
__device__ uint4 g_low2p[NPIX * 16];
__device__ uint4 g_tp[4 * NPIX * 16];   // packed conv1 outputs, per combo
__device__ uint4 g_ap[4 * NPIX * 16];   // packed conv2 outputs, per combo
__device__ uint4 g_wp[5][9216];         // prepacked weights: fe1w1,fe2w1,fe1w2,fe2w2,convw
__device__ float g_qk[4 * NT];          // Q1,K1,Q2,K2 (fp32 NCHW)
__device__ float g_r2l1[NT];
__device__ float g_l2r1[NT];

// ---------------- helpers ----------------
__device__ __forceinline__ void split_pack(float ev, float ov, u32 &hi, u32 &lo)
{
    __nv_bfloat16 eh = __float2bfloat16(ev);
    __nv_bfloat16 oh = __float2bfloat16(ov);
    __nv_bfloat16 el = __float2bfloat16(ev - __bfloat162float(eh));
    __nv_bfloat16 ol = __float2bfloat16(ov - __bfloat162float(oh));
    hi = (u32)__bfloat16_as_ushort(eh) | ((u32)__bfloat16_as_ushort(oh) << 16);
    lo = (u32)__bfloat16_as_ushort(el) | ((u32)__bfloat16_as_ushort(ol) << 16);
}

__device__ __forceinline__ void mma16816(float c[4],
                                         u32 a0, u32 a1, u32 a2, u32 a3,
                                         u32 b0, u32 b1)
{
    asm volatile(
        "mma.sync.aligned.m16n8k16.row.col.f32.bf16.bf16.f32 "
        "{%0,%1,%2,%3}, {%4,%5,%6,%7}, {%8,%9}, {%0,%1,%2,%3};"
        : "+f"(c[0]), "+f"(c[1]), "+f"(c[2]), "+f"(c[3])
        : "r"(a0), "r"(a1), "r"(a2), "r"(a3), "r"(b0), "r"(b1));
}

__device__ __forceinline__ void ldsm4(u32 f[4], u32 addr)
{
    asm volatile(
        "ldmatrix.sync.aligned.m8n8.x4.shared.b16 {%0,%1,%2,%3}, [%4];"
        : "=r"(f[0]), "=r"(f[1]), "=r"(f[2]), "=r"(f[3]) : "r"(addr));
}

__device__ __forceinline__ u64 pk2(float lo, float hi)
{
    u64 r;
    asm("mov.b64 %0, {%1,%2};" : "=l"(r) : "f"(lo), "f"(hi));
    return r;
}
__device__ __forceinline__ void upk2(u64 v, float &lo, float &hi)
{
    asm("mov.b64 {%0,%1}, %2;" : "=f"(lo), "=f"(hi) : "l"(v));
}
__device__ __forceinline__ void ffma2(u64 &d, u64 a, u64 b)
{
    asm("fma.rn.f32x2 %0, %1, %2, %0;" : "+l"(d) : "l"(a), "l"(b));
}

// =================================================================================
// Prep kernels (one launch each)
// =================================================================================
__global__ void pack_weights_all(
    const float* __restrict__ w0, const float* __restrict__ w1,
    const float* __restrict__ w2, const float* __restrict__ w3,
    const float* __restrict__ w4, uint4* __restrict__ wp)
{
    int idx = blockIdx.x * 256 + threadIdx.x;
    if (idx >= 5 * 9216) return;
    int which = idx / 9216, r = idx % 9216;
    const float* w = (which == 0) ? w0 : (which == 1) ? w1 :
                     (which == 2) ? w2 : (which == 3) ? w3 : w4;
    int tap = r >> 10, rem = r & 1023;
    int chunk = rem >> 8, rem2 = rem & 255;
    int o = rem2 >> 2, t = rem2 & 3;
    int c2a = chunk * 8 + t, c2b = c2a + 4;
    u32 h0, l0, h1, l1;
    split_pack(__ldg(&w[o * 576 + (2 * c2a) * 9 + tap]),
               __ldg(&w[o * 576 + (2 * c2a + 1) * 9 + tap]), h0, l0);
    split_pack(__ldg(&w[o * 576 + (2 * c2b) * 9 + tap]),
               __ldg(&w[o * 576 + (2 * c2b + 1) * 9 + tap]), h1, l1);
    wp[idx] = make_uint4(h0, h1, l0, l1);
}

// fp32 NCHW -> NHWC packed (uint4 per 4-channel group, 16 per pixel)
__global__ void pack_features_all(const float* __restrict__ x1,
                                  const float* __restrict__ x2,
                                  uint4* __restrict__ xp1,
                                  uint4* __restrict__ xp2)
{
    int gi = blockIdx.x * 256 + threadIdx.x;
    if (gi >= 2 * 16 * NPIX) return;
    int tsel = gi / (16 * NPIX);
    int r = gi - tsel * 16 * NPIX;
    int j = r / NPIX;
    int p = r - j * NPIX;                  // (b*HH + y)*WW + x
    const float* x = tsel ? x2 : x1;
    uint4* xp = tsel ? xp2 : xp1;
    int b = p / (HH * WW);
    int pos = p - b * HH * WW;
    const float* src = x + (size_t)(b * 64 + 4 * j) * CS + pos;
    u32 h0, l0, h1, l1;
    split_pack(src[0], src[CS], h0, l0);
    split_pack(src[2 * CS], src[3 * CS], h1, l1);
    xp[(size_t)p * 16 + j] = make_uint4(h0, l0, h1, l1);
}

// =================================================================================
// Tensor-core conv 3x3 (stride1 pad1 C64->C64), bf16x3, NHWC halo + ldmatrix.
// 256 threads = 8 warps; 16x16 pixel tile; warp = 2 image rows x 64 och.
// SMEM halo: per pixel 128B hi + 128B lo, 8 units of 16B each stored at
// (unit ^ (x&7)) -> conflict-free ldmatrix. A fragments via LDSM.x4 with
// y-reuse across dy taps (4 rows loaded per (chunk,dx), shared by 6 (mi,dy)).
// grid (12,12,16): z -> combo = z>>2, b = z&3.
// mode 1: relu -> NHWC packed ; mode 2: +skip -> NHWC packed ; mode 0: fp32 NCHW.
// =================================================================================
#define CONV_SMEM_BYTES (23040*4)   // Hhi 11520 u32 + Hlo 11520 u32 = 92160 B

__global__ void __launch_bounds__(256, 2) conv3x3_tc(
    const uint4* __restrict__ xpA, const uint4* __restrict__ xpB, int xstride_u4,
    const uint4* __restrict__ wpA, const uint4* __restrict__ wpB,
    const float* __restrict__ bsA, const float* __restrict__ bsB,
    const float* __restrict__ skA, const float* __restrict__ skB,
    float* __restrict__ yf, uint4* __restrict__ yp, int mode)
{
    extern __shared__ u32 smc[];
    u32* Hhi = smc;            // [18][20] pixels x 32 u32 (swizzled units)
    u32* Hlo = smc + 11520;

    const int bz = blockIdx.z;
    const int combo = bz >> 2, b = bz & 3;
    const uint4* xp = ((combo & 1) ? xpB : xpA) + (size_t)combo * xstride_u4;
    const uint4* wp = (combo >> 1) ? wpB : wpA;
    const float* bias = (combo >> 1) ? bsB : bsA;
    const float* skip = (combo & 1) ? skB : skA;

    const int ty = blockIdx.y, tx = blockIdx.x;
    const int tid = threadIdx.x, wid = tid >> 5, lane = tid & 31;
    const int g = lane >> 2, t = lane & 3;

    // ---- stage NHWC halo (18x18 pixels, zero-padded at image border) ----
    const int y0 = ty * 16 - 1, x0 = tx * 16 - 1;
    for (int i = tid; i < 324 * 16; i += 256) {
        int pix = i >> 4, j = i & 15;
        int yy = pix / 18, xx = pix - yy * 18;
        int gy = y0 + yy, gx = x0 + xx;
        uint4 v = make_uint4(0u, 0u, 0u, 0u);
        if (gy >= 0 && gy < HH && gx >= 0 && gx < WW)
            v = __ldg(&xp[(size_t)((b * HH + gy) * WW + gx) * 16 + j]);
        int unitoff = (yy * 20 + xx) * 32 + (((j >> 1) ^ (xx & 7)) << 2) + ((j & 1) << 1);
        *(uint2*)&Hhi[unitoff] = make_uint2(v.x, v.z);
        *(uint2*)&Hlo[unitoff] = make_uint2(v.y, v.w);
    }
    __syncthreads();

    float acc[2][8][4];
#pragma unroll
    for (int mi = 0; mi < 2; mi++)
#pragma unroll
        for (int n8 = 0; n8 < 8; n8++)
#pragma unroll
            for (int q = 0; q < 4; q++) acc[mi][n8][q] = 0.f;

    const int row0 = 2 * wid;    // warp's first image row within the tile
    const u32 hbase = (u32)__cvta_generic_to_shared(Hhi);
    const u32 lbase = (u32)__cvta_generic_to_shared(Hlo);
    const int m = lane & 15, half = lane >> 4;

    for (int ch = 0; ch < 4; ch++) {
#pragma unroll
        for (int dx = 0; dx < 3; dx++) {
            const int xm = dx + m;                       // halo x for this lane's row
            const int coff = (((ch * 2 + half) ^ (xm & 7)) << 4);   // swizzled unit, bytes
            const u32 a0 = (u32)((row0 * 20 + xm) * 128 + coff);
            // 4 halo rows (row0..row0+3) cover (mi,dy) pairs via ri = mi+dy
            u32 fh[4][4], fl[4][4];
#pragma unroll
            for (int ri = 0; ri < 4; ri++) {
                ldsm4(fh[ri], hbase + a0 + ri * 2560);   // 20 px * 128 B per halo row
                ldsm4(fl[ri], lbase + a0 + ri * 2560);
            }
#pragma unroll
            for (int dy = 0; dy < 3; dy++) {
                const uint4* wrow = wp + (((dy * 3 + dx) * 4 + ch) * 64) * 4 + t;
#pragma unroll
                for (int n8 = 0; n8 < 8; n8++) {
                    uint4 Bv = __ldg(&wrow[(n8 * 8 + g) * 4]);
#pragma unroll
                    for (int mi = 0; mi < 2; mi++) {
                        const int ri = mi + dy;
                        mma16816(acc[mi][n8], fh[ri][0], fh[ri][1], fh[ri][2], fh[ri][3], Bv.x, Bv.y);
                        mma16816(acc[mi][n8], fh[ri][0], fh[ri][1], fh[ri][2], fh[ri][3], Bv.z, Bv.w);
                        mma16816(acc[mi][n8], fl[ri][0], fl[ri][1], fl[ri][2], fl[ri][3], Bv.x, Bv.y);
                    }
                }
            }
        }
    }

    // ---- epilogue ----
    const int gyb = ty * 16 + row0, gxb = tx * 16;
    if (mode == 0) {
        float* yfc = yf + (size_t)combo * NT;
#pragma unroll
        for (int n8 = 0; n8 < 8; n8++) {
#pragma unroll
            for (int mi = 0; mi < 2; mi++) {
                const int gy = gyb + mi;
#pragma unroll
                for (int q = 0; q < 4; q++) {
                    const int och = n8 * 8 + 2 * t + (q & 1);
                    const int px  = gxb + g + ((q >= 2) ? 8 : 0);
                    yfc[((b * 64 + och) * HH + gy) * WW + px] =
                        acc[mi][n8][q] + __ldg(&bias[och]);
                }
            }
        }
    } else {
        uint2* ypc = (uint2*)(yp + (size_t)combo * (NPIX * 16));
#pragma unroll
        for (int n8 = 0; n8 < 8; n8++) {
            const int och0 = n8 * 8 + 2 * t;
            const float b0 = __ldg(&bias[och0]);
            const float b1 = __ldg(&bias[och0 + 1]);
            const int c2o = n8 * 4 + t;
#pragma unroll
            for (int mi = 0; mi < 2; mi++) {
                const int gy = gyb + mi;
#pragma unroll
                for (int hlf = 0; hlf < 2; hlf++) {
                    const int px = gxb + g + hlf * 8;
                    float v0 = acc[mi][n8][hlf * 2 + 0] + b0;
                    float v1 = acc[mi][n8][hlf * 2 + 1] + b1;
                    if (mode == 1) {
                        v0 = fmaxf(v0, 0.f);
                        v1 = fmaxf(v1, 0.f);
                    } else {
                        const int off = ((b * 64 + och0) * HH + gy) * WW + px;
                        v0 += __ldg(&skip[off]);
                        v1 += __ldg(&skip[off + CS]);
                    }
                    u32 h, l;
                    split_pack(v0, v1, h, l);
                    ypc[(size_t)((b * HH + gy) * WW + px) * 32 + c2o] = make_uint2(h, l);
                }
            }
        }
    }
}

// =================================================================================
// Fused attention (unchanged, passing): one CTA per (b, h), 256 thr.
// =================================================================================

__device__ __forceinline__ void load_feat(float* fbf, const float* __restrict__ gsrc,
                                          int rb, int tid)
{
#pragma unroll
    for (int k = 0; k < 6; k++) {
        int i4 = tid + k * 256;
        int c2 = i4 / 48, v4 = i4 % 48;
        float4 a4 = *(const float4*)(gsrc + rb + (2 * c2) * CS + v4 * 4);
        float4 b4 = *(const float4*)(gsrc + rb + (2 * c2 + 1) * CS + v4 * 4);
        float4* dst = (float4*)(fbf + (c2 * 192 + v4 * 4) * 2);
        dst[0] = make_float4(a4.x, b4.x, a4.y, b4.y);
        dst[1] = make_float4(a4.z, b4.z, a4.w, b4.w);
    }
}

__device__ __forceinline__ void compute_S(const float* __restrict__ Q, int rb,
                                          const u64* fbu, float* Sb,
                                          int wid, int lane)
{
    const int w0 = wid * 24;
    for (int gg = 0; gg < 6; gg++) {
        const int wr = w0 + gg * 4;
        u64 accp[4][6];
#pragma unroll
        for (int r = 0; r < 4; r++)
#pragma unroll
            for (int j = 0; j < 6; j++) accp[r][j] = 0ull;

        for (int c2 = 0; c2 < 32; c2++) {
            float4 q0 = __ldg((const float4*)(Q + rb + (2 * c2) * CS + wr));
            float4 q1 = __ldg((const float4*)(Q + rb + (2 * c2 + 1) * CS + wr));
            u64 aq0 = pk2(q0.x, q1.x), aq1 = pk2(q0.y, q1.y);
            u64 aq2 = pk2(q0.z, q1.z), aq3 = pk2(q0.w, q1.w);
#pragma unroll
            for (int j = 0; j < 6; j++) {
                u64 kv = fbu[c2 * 192 + lane + 32 * j];
                ffma2(accp[0][j], aq0, kv);
                ffma2(accp[1][j], aq1, kv);
                ffma2(accp[2][j], aq2, kv);
                ffma2(accp[3][j], aq3, kv);
            }
        }
#pragma unroll
        for (int r = 0; r < 4; r++)
#pragma unroll
            for (int j = 0; j < 6; j++) {
                float lo, hi;
                upk2(accp[r][j], lo, hi);
                Sb[(wr + r) * SP + lane + 32 * j] = lo + hi;
            }
    }
}

__device__ __forceinline__ void softmax_rows(float* Sb, int wid, int lane)
{
    for (int r = wid * 24; r < wid * 24 + 24; r++) {
        float v[6];
        float m = -1e30f;
#pragma unroll
        for (int j = 0; j < 6; j++) {
            v[j] = Sb[r * SP + lane + 32 * j];
            m = fmaxf(m, v[j]);
        }
#pragma unroll
        for (int o = 16; o > 0; o >>= 1)
            m = fmaxf(m, __shfl_xor_sync(0xffffffffu, m, o));
        float s = 0.f;
#pragma unroll
        for (int j = 0; j < 6; j++) { v[j] = __expf(v[j] - m); s += v[j]; }
#pragma unroll
        for (int o = 16; o > 0; o >>= 1)
            s += __shfl_xor_sync(0xffffffffu, s, o);
        float inv = 1.0f / s;
#pragma unroll
        for (int j = 0; j < 6; j++)
            Sb[r * SP + lane + 32 * j] = v[j] * inv;
    }
}

template <bool TRANSP>
__device__ __forceinline__ void apply_gemm(const u64* fbu, const float* Sb,
                                           float t[48], int wid, int lane)
{
    u64 acc2[4][6];
#pragma unroll
    for (int ci2 = 0; ci2 < 4; ci2++)
#pragma unroll
        for (int j = 0; j < 6; j++) acc2[ci2][j] = 0ull;

    const int fbase = wid * 4 * 192;
    for (int v = 0; v < 192; v += 4) {
        u64 fp[4][4];
#pragma unroll
        for (int ci2 = 0; ci2 < 4; ci2++) {
            ulonglong2 u0 = *(const ulonglong2*)(fbu + fbase + ci2 * 192 + v);
            ulonglong2 u1 = *(const ulonglong2*)(fbu + fbase + ci2 * 192 + v + 2);
            fp[ci2][0] = u0.x; fp[ci2][1] = u0.y;
            fp[ci2][2] = u1.x; fp[ci2][3] = u1.y;
        }
#pragma unroll
        for (int dv = 0; dv < 4; dv++) {
#pragma unroll
            for (int j = 0; j < 6; j++) {
                float s = TRANSP ? Sb[(v + dv) * SP + lane + 32 * j]
                                 : Sb[(lane + 32 * j) * SP + (v + dv)];
                u64 s2 = pk2(s, s);
                ffma2(acc2[0][j], fp[0][dv], s2);
                ffma2(acc2[1][j], fp[1][dv], s2);
                ffma2(acc2[2][j], fp[2][dv], s2);
                ffma2(acc2[3][j], fp[3][dv], s2);
            }
        }
    }
#pragma unroll
    for (int ci2 = 0; ci2 < 4; ci2++)
#pragma unroll
        for (int j = 0; j < 6; j++) {
            float lo, hi;
            upk2(acc2[ci2][j], lo, hi);
            t[(2 * ci2) * 6 + j] = lo;
            t[(2 * ci2 + 1) * 6 + j] = hi;
        }
}

__device__ __forceinline__ void emit_init(float* dst, float* scratch,
                                          const float* base, const float t[48],
                                          int rb, int wid, int lane)
{
    const int c0 = wid * 8;
#pragma unroll
    for (int ci = 0; ci < 8; ci++)
#pragma unroll
        for (int j = 0; j < 6; j++) {
            int off = rb + (c0 + ci) * CS + lane + 32 * j;
            float v = t[ci * 6 + j];
            scratch[off] = v;
            dst[off] = base[off] + v;
        }
}

__device__ __forceinline__ void emit_add(float* dst, const float t[48],
                                         int rb, int wid, int lane)
{
    const int c0 = wid * 8;
#pragma unroll
    for (int ci = 0; ci < 8; ci++)
#pragma unroll
        for (int j = 0; j < 6; j++) {
            int off = rb + (c0 + ci) * CS + lane + 32 * j;
            dst[off] += t[ci * 6 + j];
        }
}

__global__ void __launch_bounds__(256, 1) attn_kernel(
    const float* __restrict__ low1, const float* __restrict__ low2,
    const float* __restrict__ Q1, const float* __restrict__ K1,
    const float* __restrict__ Q2, const float* __restrict__ K2,
    float* __restrict__ r2l1s, float* __restrict__ l2r1s,
    float* __restrict__ outL, float* __restrict__ outR)
{
    extern __shared__ float smf[];
    float* Sb  = smf;
    float* fbf = smf + 192 * SP;
    const u64* fbu = (const u64*)fbf;

    const int h = blockIdx.x, b = blockIdx.y;
    const int tid = threadIdx.x, wid = tid >> 5, lane = tid & 31;
    const int rb = b * 64 * CS + h * WW;
    float t[48];

    load_feat(fbf, K1, rb, tid); __syncthreads();
    compute_S(Q1, rb, fbu, Sb, wid, lane); __syncthreads();
    softmax_rows(Sb, wid, lane); __syncthreads();

    load_feat(fbf, low2, rb, tid); __syncthreads();
    apply_gemm<false>(fbu, Sb, t, wid, lane);
    emit_init(outL, r2l1s, low1, t, rb, wid, lane);
    __syncthreads();

    load_feat(fbf, low1, rb, tid); __syncthreads();
    apply_gemm<true>(fbu, Sb, t, wid, lane);
    emit_init(outR, l2r1s, low2, t, rb, wid, lane);
    __syncthreads();

    load_feat(fbf, K2, rb, tid); __syncthreads();
    compute_S(Q2, rb, fbu, Sb, wid, lane); __syncthreads();
    softmax_rows(Sb, wid, lane); __syncthreads();

    load_feat(fbf, low2, rb, tid); __syncthreads();
    apply_gemm<false>(fbu, Sb, t, wid, lane);
    emit_add(outL, t, rb, wid, lane); __syncthreads();

    load_feat(fbf, low1, rb, tid); __syncthreads();
    apply_gemm<true>(fbu, Sb, t, wid, lane);
    emit_add(outR, t, rb, wid, lane); __syncthreads();

    load_feat(fbf, l2r1s, rb, tid); __syncthreads();
    apply_gemm<false>(fbu, Sb, t, wid, lane);
    emit_add(outL, t, rb, wid, lane); __syncthreads();

    load_feat(fbf, r2l1s, rb, tid); __syncthreads();
    apply_gemm<true>(fbu, Sb, t, wid, lane);
    emit_add(outR, t, rb, wid, lane);
}

// =================================================================================
extern "C" void kernel_launch(void* const* d_in, const int* in_sizes, int n_in,
                              void* d_out, int out_size)
{
    const float* low1   = (const float*)d_in[0];
    const float* low2   = (const float*)d_in[1];
    const float* fe1_w1 = (const float*)d_in[2];
    const float* fe1_b1 = (const float*)d_in[3];
    const float* fe1_w2 = (const float*)d_in[4];
    const float* fe1_b2 = (const float*)d_in[5];
    const float* fe2_w1 = (const float*)d_in[6];
    const float* fe2_b1 = (const float*)d_in[7];
    const float* fe2_w2 = (const float*)d_in[8];
    const float* fe2_b2 = (const float*)d_in[9];
    const float* conv_w = (const float*)d_in[10];
    const float* conv_b = (const float*)d_in[11];
    float* out = (float*)d_out;

    uint4 *low1p, *low2p, *tp, *ap, *wp;
    float *qk, *r2l1, *l2r1;
    cudaGetSymbolAddress((void**)&low1p, g_low1p);
    cudaGetSymbolAddress((void**)&low2p, g_low2p);
    cudaGetSymbolAddress((void**)&tp,    g_tp);
    cudaGetSymbolAddress((void**)&ap,    g_ap);
    cudaGetSymbolAddress((void**)&wp,    g_wp);
    cudaGetSymbolAddress((void**)&qk,    g_qk);
    cudaGetSymbolAddress((void**)&r2l1,  g_r2l1);
    cudaGetSymbolAddress((void**)&l2r1,  g_l2r1);

    uint4* wp_fe1w1 = wp + 0 * 9216;
    uint4* wp_fe2w1 = wp + 1 * 9216;
    uint4* wp_fe1w2 = wp + 2 * 9216;
    uint4* wp_fe2w2 = wp + 3 * 9216;
    uint4* wp_convw = wp + 4 * 9216;

    cudaFuncSetAttribute(conv3x3_tc,
                         cudaFuncAttributeMaxDynamicSharedMemorySize,
                         CONV_SMEM_BYTES);
    const int attn_smem = (192 * SP + 2 * 32 * 192) * (int)sizeof(float); // 197376
    cudaFuncSetAttribute(attn_kernel,
                         cudaFuncAttributeMaxDynamicSharedMemorySize, attn_smem);

    const dim3 cgrid(WW / 16, HH / 16, 4 * BB);

    // launch 0: all weight packing
    pack_weights_all<<<180, 256>>>(fe1_w1, fe2_w1, fe1_w2, fe2_w2, conv_w, wp);
    // launch 1: both feature packs (NHWC)
    pack_features_all<<<(2 * 16 * NPIX + 255) / 256, 256>>>(low1, low2, low1p, low2p);

    // launch 2: conv stage 1: t[combo] = relu(conv(low, w1) + b1)   (NHWC packed out)
    conv3x3_tc<<<cgrid, 256, CONV_SMEM_BYTES>>>(
        low1p, low2p, 0, wp_fe1w1, wp_fe2w1, fe1_b1, fe2_b1,
        nullptr, nullptr, nullptr, tp, 1);
    // launch 3: conv stage 2: a[combo] = low + conv(t, w2) + b2     (NHWC packed out)
    conv3x3_tc<<<cgrid, 256, CONV_SMEM_BYTES>>>(
        tp, tp, NPIX * 16, wp_fe1w2, wp_fe2w2, fe1_b2, fe2_b2,
        low1, low2, nullptr, ap, 2);
    // launch 4: conv stage 3: qk[combo] = conv(a, conv_w) + conv_b  (fp32 NCHW out)
    conv3x3_tc<<<cgrid, 256, CONV_SMEM_BYTES>>>(
        ap, ap, NPIX * 16, wp_convw, wp_convw, conv_b, conv_b,
        nullptr, nullptr, qk, nullptr, 0);

    // launch 5: attention
    attn_kernel<<<dim3(HH, BB), 256, attn_smem>>>(
        low1, low2, qk, qk + NT, qk + 2 * NT, qk + 3 * NT,
        r2l1, l2r1, out, out + NT);
}

// round 7
// speedup vs baseline: 1.3468x; 1.0443x over previous
#include <cuda_runtime.h>
#include <cuda_bf16.h>

typedef unsigned int u32;
typedef unsigned long long u64;

// Problem constants
#define BB 4
#define CC 64
#define HH 192
#define WW 192
#define CS (HH*WW)            // channel stride = 36864
#define NT (BB*CC*HH*WW)      // elems per [B,C,H,W] fp32 tensor
#define NPIX (BB*HH*WW)       // pixels per tensor = 147456
#define SP 193                // padded row stride for score matrix in SMEM

// ---------------- static scratch (no runtime allocation allowed) ----------------
__device__ uint4 g_low1p[NPIX * 16];
__device__ uint4 g_low2p[NPIX * 16];
__device__ uint4 g_tp[4 * NPIX * 16];   // packed conv1 outputs, per combo
__device__ uint4 g_ap[4 * NPIX * 16];   // packed conv2 outputs, per combo
__device__ uint4 g_wp[5][9216];         // prepacked weights
__device__ float g_qk[4 * NT];          // Q1,K1,Q2,K2 (fp32 NCHW)
__device__ float g_r2l1[NT];
__device__ float g_l2r1[NT];

// ---------------- helpers ----------------
__device__ __forceinline__ void split_pack(float ev, float ov, u32 &hi, u32 &lo)
{
    __nv_bfloat16 eh = __float2bfloat16(ev);
    __nv_bfloat16 oh = __float2bfloat16(ov);
    __nv_bfloat16 el = __float2bfloat16(ev - __bfloat162float(eh));
    __nv_bfloat16 ol = __float2bfloat16(ov - __bfloat162float(oh));
    hi = (u32)__bfloat16_as_ushort(eh) | ((u32)__bfloat16_as_ushort(oh) << 16);
    lo = (u32)__bfloat16_as_ushort(el) | ((u32)__bfloat16_as_ushort(ol) << 16);
}

__device__ __forceinline__ void mma16816(float c[4],
                                         u32 a0, u32 a1, u32 a2, u32 a3,
                                         u32 b0, u32 b1)
{
    asm volatile(
        "mma.sync.aligned.m16n8k16.row.col.f32.bf16.bf16.f32 "
        "{%0,%1,%2,%3}, {%4,%5,%6,%7}, {%8,%9}, {%0,%1,%2,%3};"
        : "+f"(c[0]), "+f"(c[1]), "+f"(c[2]), "+f"(c[3])
        : "r"(a0), "r"(a1), "r"(a2), "r"(a3), "r"(b0), "r"(b1));
}

__device__ __forceinline__ void ldsm4(u32 f[4], u32 addr)
{
    asm volatile(
        "ldmatrix.sync.aligned.m8n8.x4.shared.b16 {%0,%1,%2,%3}, [%4];"
        : "=r"(f[0]), "=r"(f[1]), "=r"(f[2]), "=r"(f[3]) : "r"(addr));
}

__device__ __forceinline__ u64 pk2(float lo, float hi)
{
    u64 r;
    asm("mov.b64 %0, {%1,%2};" : "=l"(r) : "f"(lo), "f"(hi));
    return r;
}
__device__ __forceinline__ void upk2(u64 v, float &lo, float &hi)
{
    asm("mov.b64 {%0,%1}, %2;" : "=f"(lo), "=f"(hi) : "l"(v));
}
__device__ __forceinline__ void ffma2(u64 &d, u64 a, u64 b)
{
    asm("fma.rn.f32x2 %0, %1, %2, %0;" : "+l"(d) : "l"(a), "l"(b));
}

// =================================================================================
// Prep kernels (one launch each)
// =================================================================================
__global__ void pack_weights_all(
    const float* __restrict__ w0, const float* __restrict__ w1,
    const float* __restrict__ w2, const float* __restrict__ w3,
    const float* __restrict__ w4, uint4* __restrict__ wp)
{
    int idx = blockIdx.x * 256 + threadIdx.x;
    if (idx >= 5 * 9216) return;
    int which = idx / 9216, r = idx % 9216;
    const float* w = (which == 0) ? w0 : (which == 1) ? w1 :
                     (which == 2) ? w2 : (which == 3) ? w3 : w4;
    int tap = r >> 10, rem = r & 1023;
    int chunk = rem >> 8, rem2 = rem & 255;
    int o = rem2 >> 2, t = rem2 & 3;
    int c2a = chunk * 8 + t, c2b = c2a + 4;
    u32 h0, l0, h1, l1;
    split_pack(__ldg(&w[o * 576 + (2 * c2a) * 9 + tap]),
               __ldg(&w[o * 576 + (2 * c2a + 1) * 9 + tap]), h0, l0);
    split_pack(__ldg(&w[o * 576 + (2 * c2b) * 9 + tap]),
               __ldg(&w[o * 576 + (2 * c2b + 1) * 9 + tap]), h1, l1);
    wp[idx] = make_uint4(h0, h1, l0, l1);
}

__global__ void pack_features_all(const float* __restrict__ x1,
                                  const float* __restrict__ x2,
                                  uint4* __restrict__ xp1,
                                  uint4* __restrict__ xp2)
{
    int gi = blockIdx.x * 256 + threadIdx.x;
    if (gi >= 2 * 16 * NPIX) return;
    int tsel = gi / (16 * NPIX);
    int r = gi - tsel * 16 * NPIX;
    int j = r / NPIX;
    int p = r - j * NPIX;
    const float* x = tsel ? x2 : x1;
    uint4* xp = tsel ? xp2 : xp1;
    int b = p / (HH * WW);
    int pos = p - b * HH * WW;
    const float* src = x + (size_t)(b * 64 + 4 * j) * CS + pos;
    u32 h0, l0, h1, l1;
    split_pack(src[0], src[CS], h0, l0);
    split_pack(src[2 * CS], src[3 * CS], h1, l1);
    xp[(size_t)p * 16 + j] = make_uint4(h0, l0, h1, l1);
}

// =================================================================================
// Tensor-core conv 3x3 (unchanged from R6 — 291us/stage, tensor=74.7%)
// =================================================================================
#define CONV_SMEM_BYTES (23040*4)

__global__ void __launch_bounds__(256, 2) conv3x3_tc(
    const uint4* __restrict__ xpA, const uint4* __restrict__ xpB, int xstride_u4,
    const uint4* __restrict__ wpA, const uint4* __restrict__ wpB,
    const float* __restrict__ bsA, const float* __restrict__ bsB,
    const float* __restrict__ skA, const float* __restrict__ skB,
    float* __restrict__ yf, uint4* __restrict__ yp, int mode)
{
    extern __shared__ u32 smc[];
    u32* Hhi = smc;
    u32* Hlo = smc + 11520;

    const int bz = blockIdx.z;
    const int combo = bz >> 2, b = bz & 3;
    const uint4* xp = ((combo & 1) ? xpB : xpA) + (size_t)combo * xstride_u4;
    const uint4* wp = (combo >> 1) ? wpB : wpA;
    const float* bias = (combo >> 1) ? bsB : bsA;
    const float* skip = (combo & 1) ? skB : skA;

    const int ty = blockIdx.y, tx = blockIdx.x;
    const int tid = threadIdx.x, wid = tid >> 5, lane = tid & 31;
    const int g = lane >> 2, t = lane & 3;

    const int y0 = ty * 16 - 1, x0 = tx * 16 - 1;
    for (int i = tid; i < 324 * 16; i += 256) {
        int pix = i >> 4, j = i & 15;
        int yy = pix / 18, xx = pix - yy * 18;
        int gy = y0 + yy, gx = x0 + xx;
        uint4 v = make_uint4(0u, 0u, 0u, 0u);
        if (gy >= 0 && gy < HH && gx >= 0 && gx < WW)
            v = __ldg(&xp[(size_t)((b * HH + gy) * WW + gx) * 16 + j]);
        int unitoff = (yy * 20 + xx) * 32 + (((j >> 1) ^ (xx & 7)) << 2) + ((j & 1) << 1);
        *(uint2*)&Hhi[unitoff] = make_uint2(v.x, v.z);
        *(uint2*)&Hlo[unitoff] = make_uint2(v.y, v.w);
    }
    __syncthreads();

    float acc[2][8][4];
#pragma unroll
    for (int mi = 0; mi < 2; mi++)
#pragma unroll
        for (int n8 = 0; n8 < 8; n8++)
#pragma unroll
            for (int q = 0; q < 4; q++) acc[mi][n8][q] = 0.f;

    const int row0 = 2 * wid;
    const u32 hbase = (u32)__cvta_generic_to_shared(Hhi);
    const u32 lbase = (u32)__cvta_generic_to_shared(Hlo);
    const int m = lane & 15, half = lane >> 4;

    for (int ch = 0; ch < 4; ch++) {
#pragma unroll
        for (int dx = 0; dx < 3; dx++) {
            const int xm = dx + m;
            const int coff = (((ch * 2 + half) ^ (xm & 7)) << 4);
            const u32 a0 = (u32)((row0 * 20 + xm) * 128 + coff);
            u32 fh[4][4], fl[4][4];
#pragma unroll
            for (int ri = 0; ri < 4; ri++) {
                ldsm4(fh[ri], hbase + a0 + ri * 2560);
                ldsm4(fl[ri], lbase + a0 + ri * 2560);
            }
#pragma unroll
            for (int dy = 0; dy < 3; dy++) {
                const uint4* wrow = wp + (((dy * 3 + dx) * 4 + ch) * 64) * 4 + t;
#pragma unroll
                for (int n8 = 0; n8 < 8; n8++) {
                    uint4 Bv = __ldg(&wrow[(n8 * 8 + g) * 4]);
#pragma unroll
                    for (int mi = 0; mi < 2; mi++) {
                        const int ri = mi + dy;
                        mma16816(acc[mi][n8], fh[ri][0], fh[ri][1], fh[ri][2], fh[ri][3], Bv.x, Bv.y);
                        mma16816(acc[mi][n8], fh[ri][0], fh[ri][1], fh[ri][2], fh[ri][3], Bv.z, Bv.w);
                        mma16816(acc[mi][n8], fl[ri][0], fl[ri][1], fl[ri][2], fl[ri][3], Bv.x, Bv.y);
                    }
                }
            }
        }
    }

    const int gyb = ty * 16 + row0, gxb = tx * 16;
    if (mode == 0) {
        float* yfc = yf + (size_t)combo * NT;
#pragma unroll
        for (int n8 = 0; n8 < 8; n8++) {
#pragma unroll
            for (int mi = 0; mi < 2; mi++) {
                const int gy = gyb + mi;
#pragma unroll
                for (int q = 0; q < 4; q++) {
                    const int och = n8 * 8 + 2 * t + (q & 1);
                    const int px  = gxb + g + ((q >= 2) ? 8 : 0);
                    yfc[((b * 64 + och) * HH + gy) * WW + px] =
                        acc[mi][n8][q] + __ldg(&bias[och]);
                }
            }
        }
    } else {
        uint2* ypc = (uint2*)(yp + (size_t)combo * (NPIX * 16));
#pragma unroll
        for (int n8 = 0; n8 < 8; n8++) {
            const int och0 = n8 * 8 + 2 * t;
            const float b0 = __ldg(&bias[och0]);
            const float b1 = __ldg(&bias[och0 + 1]);
            const int c2o = n8 * 4 + t;
#pragma unroll
            for (int mi = 0; mi < 2; mi++) {
                const int gy = gyb + mi;
#pragma unroll
                for (int hlf = 0; hlf < 2; hlf++) {
                    const int px = gxb + g + hlf * 8;
                    float v0 = acc[mi][n8][hlf * 2 + 0] + b0;
                    float v1 = acc[mi][n8][hlf * 2 + 1] + b1;
                    if (mode == 1) {
                        v0 = fmaxf(v0, 0.f);
                        v1 = fmaxf(v1, 0.f);
                    } else {
                        const int off = ((b * 64 + och0) * HH + gy) * WW + px;
                        v0 += __ldg(&skip[off]);
                        v1 += __ldg(&skip[off + CS]);
                    }
                    u32 h, l;
                    split_pack(v0, v1, h, l);
                    ypc[(size_t)((b * HH + gy) * WW + px) * 32 + c2o] = make_uint2(h, l);
                }
            }
        }
    }
}

// =================================================================================
// Fused attention: one CTA per (b, h). NOW 512 threads = 16 warps (4/SMSP)
// for latency hiding; per-warp work halved, same total instruction count.
// SMEM: Sb[192][193] fp32 scores + fb channel-pair-interleaved features.
// =================================================================================

__device__ __forceinline__ void load_feat(float* fbf, const float* __restrict__ gsrc,
                                          int rb, int tid)
{
#pragma unroll
    for (int k = 0; k < 3; k++) {
        int i4 = tid + k * 512;          // 0..1535 over (c2, v4)
        int c2 = i4 / 48, v4 = i4 % 48;
        float4 a4 = *(const float4*)(gsrc + rb + (2 * c2) * CS + v4 * 4);
        float4 b4 = *(const float4*)(gsrc + rb + (2 * c2 + 1) * CS + v4 * 4);
        float4* dst = (float4*)(fbf + (c2 * 192 + v4 * 4) * 2);
        dst[0] = make_float4(a4.x, b4.x, a4.y, b4.y);
        dst[1] = make_float4(a4.z, b4.z, a4.w, b4.w);
    }
}

// S[w][v] = sum_c Q[c][w] * K[c][v] ; warp owns 12 rows (3 groups of 4)
__device__ __forceinline__ void compute_S(const float* __restrict__ Q, int rb,
                                          const u64* fbu, float* Sb,
                                          int wid, int lane)
{
    const int w0 = wid * 12;
    for (int gg = 0; gg < 3; gg++) {
        const int wr = w0 + gg * 4;
        u64 accp[4][6];
#pragma unroll
        for (int r = 0; r < 4; r++)
#pragma unroll
            for (int j = 0; j < 6; j++) accp[r][j] = 0ull;

        for (int c2 = 0; c2 < 32; c2++) {
            float4 q0 = __ldg((const float4*)(Q + rb + (2 * c2) * CS + wr));
            float4 q1 = __ldg((const float4*)(Q + rb + (2 * c2 + 1) * CS + wr));
            u64 aq0 = pk2(q0.x, q1.x), aq1 = pk2(q0.y, q1.y);
            u64 aq2 = pk2(q0.z, q1.z), aq3 = pk2(q0.w, q1.w);
#pragma unroll
            for (int j = 0; j < 6; j++) {
                u64 kv = fbu[c2 * 192 + lane + 32 * j];
                ffma2(accp[0][j], aq0, kv);
                ffma2(accp[1][j], aq1, kv);
                ffma2(accp[2][j], aq2, kv);
                ffma2(accp[3][j], aq3, kv);
            }
        }
#pragma unroll
        for (int r = 0; r < 4; r++)
#pragma unroll
            for (int j = 0; j < 6; j++) {
                float lo, hi;
                upk2(accp[r][j], lo, hi);
                Sb[(wr + r) * SP + lane + 32 * j] = lo + hi;
            }
    }
}

__device__ __forceinline__ void softmax_rows(float* Sb, int wid, int lane)
{
    for (int r = wid * 12; r < wid * 12 + 12; r++) {
        float v[6];
        float m = -1e30f;
#pragma unroll
        for (int j = 0; j < 6; j++) {
            v[j] = Sb[r * SP + lane + 32 * j];
            m = fmaxf(m, v[j]);
        }
#pragma unroll
        for (int o = 16; o > 0; o >>= 1)
            m = fmaxf(m, __shfl_xor_sync(0xffffffffu, m, o));
        float s = 0.f;
#pragma unroll
        for (int j = 0; j < 6; j++) { v[j] = __expf(v[j] - m); s += v[j]; }
#pragma unroll
        for (int o = 16; o > 0; o >>= 1)
            s += __shfl_xor_sync(0xffffffffu, s, o);
        float inv = 1.0f / s;
#pragma unroll
        for (int j = 0; j < 6; j++)
            Sb[r * SP + lane + 32 * j] = v[j] * inv;
    }
}

// warp owns 4 channels (2 c2 pairs); t[24] accumulators
template <bool TRANSP>
__device__ __forceinline__ void apply_gemm(const u64* fbu, const float* Sb,
                                           float t[24], int wid, int lane)
{
    u64 acc2[2][6];
#pragma unroll
    for (int ci2 = 0; ci2 < 2; ci2++)
#pragma unroll
        for (int j = 0; j < 6; j++) acc2[ci2][j] = 0ull;

    const int fbase = wid * 2 * 192;
    for (int v = 0; v < 192; v += 4) {
        u64 fp[2][4];
#pragma unroll
        for (int ci2 = 0; ci2 < 2; ci2++) {
            ulonglong2 u0 = *(const ulonglong2*)(fbu + fbase + ci2 * 192 + v);
            ulonglong2 u1 = *(const ulonglong2*)(fbu + fbase + ci2 * 192 + v + 2);
            fp[ci2][0] = u0.x; fp[ci2][1] = u0.y;
            fp[ci2][2] = u1.x; fp[ci2][3] = u1.y;
        }
#pragma unroll
        for (int dv = 0; dv < 4; dv++) {
#pragma unroll
            for (int j = 0; j < 6; j++) {
                float s = TRANSP ? Sb[(v + dv) * SP + lane + 32 * j]
                                 : Sb[(lane + 32 * j) * SP + (v + dv)];
                u64 s2 = pk2(s, s);
                ffma2(acc2[0][j], fp[0][dv], s2);
                ffma2(acc2[1][j], fp[1][dv], s2);
            }
        }
    }
#pragma unroll
    for (int ci2 = 0; ci2 < 2; ci2++)
#pragma unroll
        for (int j = 0; j < 6; j++) {
            float lo, hi;
            upk2(acc2[ci2][j], lo, hi);
            t[(2 * ci2) * 6 + j] = lo;
            t[(2 * ci2 + 1) * 6 + j] = hi;
        }
}

__device__ __forceinline__ void emit_init(float* dst, float* scratch,
                                          const float* base, const float t[24],
                                          int rb, int wid, int lane)
{
    const int c0 = wid * 4;
#pragma unroll
    for (int ci = 0; ci < 4; ci++)
#pragma unroll
        for (int j = 0; j < 6; j++) {
            int off = rb + (c0 + ci) * CS + lane + 32 * j;
            float v = t[ci * 6 + j];
            scratch[off] = v;
            dst[off] = base[off] + v;
        }
}

__device__ __forceinline__ void emit_add(float* dst, const float t[24],
                                         int rb, int wid, int lane)
{
    const int c0 = wid * 4;
#pragma unroll
    for (int ci = 0; ci < 4; ci++)
#pragma unroll
        for (int j = 0; j < 6; j++) {
            int off = rb + (c0 + ci) * CS + lane + 32 * j;
            dst[off] += t[ci * 6 + j];
        }
}

__global__ void __launch_bounds__(512, 1) attn_kernel(
    const float* __restrict__ low1, const float* __restrict__ low2,
    const float* __restrict__ Q1, const float* __restrict__ K1,
    const float* __restrict__ Q2, const float* __restrict__ K2,
    float* __restrict__ r2l1s, float* __restrict__ l2r1s,
    float* __restrict__ outL, float* __restrict__ outR)
{
    extern __shared__ float smf[];
    float* Sb  = smf;
    float* fbf = smf + 192 * SP;
    const u64* fbu = (const u64*)fbf;

    const int h = blockIdx.x, b = blockIdx.y;
    const int tid = threadIdx.x, wid = tid >> 5, lane = tid & 31;
    const int rb = b * 64 * CS + h * WW;
    float t[24];

    load_feat(fbf, K1, rb, tid); __syncthreads();
    compute_S(Q1, rb, fbu, Sb, wid, lane); __syncthreads();
    softmax_rows(Sb, wid, lane); __syncthreads();

    load_feat(fbf, low2, rb, tid); __syncthreads();
    apply_gemm<false>(fbu, Sb, t, wid, lane);
    emit_init(outL, r2l1s, low1, t, rb, wid, lane);
    __syncthreads();

    load_feat(fbf, low1, rb, tid); __syncthreads();
    apply_gemm<true>(fbu, Sb, t, wid, lane);
    emit_init(outR, l2r1s, low2, t, rb, wid, lane);
    __syncthreads();

    load_feat(fbf, K2, rb, tid); __syncthreads();
    compute_S(Q2, rb, fbu, Sb, wid, lane); __syncthreads();
    softmax_rows(Sb, wid, lane); __syncthreads();

    load_feat(fbf, low2, rb, tid); __syncthreads();
    apply_gemm<false>(fbu, Sb, t, wid, lane);
    emit_add(outL, t, rb, wid, lane); __syncthreads();

    load_feat(fbf, low1, rb, tid); __syncthreads();
    apply_gemm<true>(fbu, Sb, t, wid, lane);
    emit_add(outR, t, rb, wid, lane); __syncthreads();

    load_feat(fbf, l2r1s, rb, tid); __syncthreads();
    apply_gemm<false>(fbu, Sb, t, wid, lane);
    emit_add(outL, t, rb, wid, lane); __syncthreads();

    load_feat(fbf, r2l1s, rb, tid); __syncthreads();
    apply_gemm<true>(fbu, Sb, t, wid, lane);
    emit_add(outR, t, rb, wid, lane);
}

// =================================================================================
extern "C" void kernel_launch(void* const* d_in, const int* in_sizes, int n_in,
                              void* d_out, int out_size)
{
    const float* low1   = (const float*)d_in[0];
    const float* low2   = (const float*)d_in[1];
    const float* fe1_w1 = (const float*)d_in[2];
    const float* fe1_b1 = (const float*)d_in[3];
    const float* fe1_w2 = (const float*)d_in[4];
    const float* fe1_b2 = (const float*)d_in[5];
    const float* fe2_w1 = (const float*)d_in[6];
    const float* fe2_b1 = (const float*)d_in[7];
    const float* fe2_w2 = (const float*)d_in[8];
    const float* fe2_b2 = (const float*)d_in[9];
    const float* conv_w = (const float*)d_in[10];
    const float* conv_b = (const float*)d_in[11];
    float* out = (float*)d_out;

    uint4 *low1p, *low2p, *tp, *ap, *wp;
    float *qk, *r2l1, *l2r1;
    cudaGetSymbolAddress((void**)&low1p, g_low1p);
    cudaGetSymbolAddress((void**)&low2p, g_low2p);
    cudaGetSymbolAddress((void**)&tp,    g_tp);
    cudaGetSymbolAddress((void**)&ap,    g_ap);
    cudaGetSymbolAddress((void**)&wp,    g_wp);
    cudaGetSymbolAddress((void**)&qk,    g_qk);
    cudaGetSymbolAddress((void**)&r2l1,  g_r2l1);
    cudaGetSymbolAddress((void**)&l2r1,  g_l2r1);

    uint4* wp_fe1w1 = wp + 0 * 9216;
    uint4* wp_fe2w1 = wp + 1 * 9216;
    uint4* wp_fe1w2 = wp + 2 * 9216;
    uint4* wp_fe2w2 = wp + 3 * 9216;
    uint4* wp_convw = wp + 4 * 9216;

    cudaFuncSetAttribute(conv3x3_tc,
                         cudaFuncAttributeMaxDynamicSharedMemorySize,
                         CONV_SMEM_BYTES);
    const int attn_smem = (192 * SP + 2 * 32 * 192) * (int)sizeof(float); // 197376
    cudaFuncSetAttribute(attn_kernel,
                         cudaFuncAttributeMaxDynamicSharedMemorySize, attn_smem);

    const dim3 cgrid(WW / 16, HH / 16, 4 * BB);

    pack_weights_all<<<180, 256>>>(fe1_w1, fe2_w1, fe1_w2, fe2_w2, conv_w, wp);
    pack_features_all<<<(2 * 16 * NPIX + 255) / 256, 256>>>(low1, low2, low1p, low2p);

    conv3x3_tc<<<cgrid, 256, CONV_SMEM_BYTES>>>(
        low1p, low2p, 0, wp_fe1w1, wp_fe2w1, fe1_b1, fe2_b1,
        nullptr, nullptr, nullptr, tp, 1);
    conv3x3_tc<<<cgrid, 256, CONV_SMEM_BYTES>>>(
        tp, tp, NPIX * 16, wp_fe1w2, wp_fe2w2, fe1_b2, fe2_b2,
        low1, low2, nullptr, ap, 2);
    conv3x3_tc<<<cgrid, 256, CONV_SMEM_BYTES>>>(
        ap, ap, NPIX * 16, wp_convw, wp_convw, conv_b, conv_b,
        nullptr, nullptr, qk, nullptr, 0);

    attn_kernel<<<dim3(HH, BB), 512, attn_smem>>>(
        low1, low2, qk, qk + NT, qk + 2 * NT, qk + 3 * NT,
        r2l1, l2r1, out, out + NT);
}

// round 8
// speedup vs baseline: 1.7401x; 1.2920x over previous
#include <cuda_runtime.h>
#include <cuda_bf16.h>

typedef unsigned int u32;
typedef unsigned long long u64;

// Problem constants
#define BB 4
#define CC 64
#define HH 192
#define WW 192
#define CS (HH*WW)            // channel stride = 36864
#define NT (BB*CC*HH*WW)      // elems per [B,C,H,W] fp32 tensor
#define NPIX (BB*HH*WW)       // pixels per tensor = 147456

// ---------------- static scratch (no runtime allocation allowed) ----------------
// NHWC packed feature format: per pixel 16 uint4; uint4 j = {hi(c2=2j), lo(2j),
// hi(2j+1), lo(2j+1)}; c2 pair = channels (2c2, 2c2+1); hi/lo = bf16x2 split.
__device__ uint4 g_low1p[NPIX * 16];
__device__ uint4 g_low2p[NPIX * 16];
__device__ uint4 g_tp[4 * NPIX * 16];   // packed conv1 outputs, per combo
__device__ uint4 g_ap[4 * NPIX * 16];   // packed conv2 outputs, per combo
__device__ uint4 g_qkp[4 * NPIX * 16];  // packed conv3 outputs: Q1,K1,Q2,K2
__device__ uint4 g_wp[5][9216];         // prepacked weights
__device__ float g_r2l1[NT];
__device__ float g_l2r1[NT];

// ---------------- helpers ----------------
__device__ __forceinline__ void split_pack(float ev, float ov, u32 &hi, u32 &lo)
{
    __nv_bfloat16 eh = __float2bfloat16(ev);
    __nv_bfloat16 oh = __float2bfloat16(ov);
    __nv_bfloat16 el = __float2bfloat16(ev - __bfloat162float(eh));
    __nv_bfloat16 ol = __float2bfloat16(ov - __bfloat162float(oh));
    hi = (u32)__bfloat16_as_ushort(eh) | ((u32)__bfloat16_as_ushort(oh) << 16);
    lo = (u32)__bfloat16_as_ushort(el) | ((u32)__bfloat16_as_ushort(ol) << 16);
}

__device__ __forceinline__ void mma16816(float c[4],
                                         u32 a0, u32 a1, u32 a2, u32 a3,
                                         u32 b0, u32 b1)
{
    asm volatile(
        "mma.sync.aligned.m16n8k16.row.col.f32.bf16.bf16.f32 "
        "{%0,%1,%2,%3}, {%4,%5,%6,%7}, {%8,%9}, {%0,%1,%2,%3};"
        : "+f"(c[0]), "+f"(c[1]), "+f"(c[2]), "+f"(c[3])
        : "r"(a0), "r"(a1), "r"(a2), "r"(a3), "r"(b0), "r"(b1));
}

__device__ __forceinline__ void ldsm4(u32 f[4], u32 addr)
{
    asm volatile(
        "ldmatrix.sync.aligned.m8n8.x4.shared.b16 {%0,%1,%2,%3}, [%4];"
        : "=r"(f[0]), "=r"(f[1]), "=r"(f[2]), "=r"(f[3]) : "r"(addr));
}

__device__ __forceinline__ void ldsm4t(u32 f[4], u32 addr)
{
    asm volatile(
        "ldmatrix.sync.aligned.m8n8.x4.trans.shared.b16 {%0,%1,%2,%3}, [%4];"
        : "=r"(f[0]), "=r"(f[1]), "=r"(f[2]), "=r"(f[3]) : "r"(addr));
}

// =================================================================================
// Prep kernels (one launch each)
// =================================================================================
__global__ void pack_weights_all(
    const float* __restrict__ w0, const float* __restrict__ w1,
    const float* __restrict__ w2, const float* __restrict__ w3,
    const float* __restrict__ w4, uint4* __restrict__ wp)
{
    int idx = blockIdx.x * 256 + threadIdx.x;
    if (idx >= 5 * 9216) return;
    int which = idx / 9216, r = idx % 9216;
    const float* w = (which == 0) ? w0 : (which == 1) ? w1 :
                     (which == 2) ? w2 : (which == 3) ? w3 : w4;
    int tap = r >> 10, rem = r & 1023;
    int chunk = rem >> 8, rem2 = rem & 255;
    int o = rem2 >> 2, t = rem2 & 3;
    int c2a = chunk * 8 + t, c2b = c2a + 4;
    u32 h0, l0, h1, l1;
    split_pack(__ldg(&w[o * 576 + (2 * c2a) * 9 + tap]),
               __ldg(&w[o * 576 + (2 * c2a + 1) * 9 + tap]), h0, l0);
    split_pack(__ldg(&w[o * 576 + (2 * c2b) * 9 + tap]),
               __ldg(&w[o * 576 + (2 * c2b + 1) * 9 + tap]), h1, l1);
    wp[idx] = make_uint4(h0, h1, l0, l1);
}

__global__ void pack_features_all(const float* __restrict__ x1,
                                  const float* __restrict__ x2,
                                  uint4* __restrict__ xp1,
                                  uint4* __restrict__ xp2)
{
    int gi = blockIdx.x * 256 + threadIdx.x;
    if (gi >= 2 * 16 * NPIX) return;
    int tsel = gi / (16 * NPIX);
    int r = gi - tsel * 16 * NPIX;
    int j = r / NPIX;
    int p = r - j * NPIX;
    const float* x = tsel ? x2 : x1;
    uint4* xp = tsel ? xp2 : xp1;
    int b = p / (HH * WW);
    int pos = p - b * HH * WW;
    const float* src = x + (size_t)(b * 64 + 4 * j) * CS + pos;
    u32 h0, l0, h1, l1;
    split_pack(src[0], src[CS], h0, l0);
    split_pack(src[2 * CS], src[3 * CS], h1, l1);
    xp[(size_t)p * 16 + j] = make_uint4(h0, l0, h1, l1);
}

// =================================================================================
// Tensor-core conv 3x3 (R6 design). mode 1: relu->packed; mode 2: +skip->packed;
// mode 3: bias only->packed (Q/K for attention).
// =================================================================================
#define CONV_SMEM_BYTES (23040*4)

__global__ void __launch_bounds__(256, 2) conv3x3_tc(
    const uint4* __restrict__ xpA, const uint4* __restrict__ xpB, int xstride_u4,
    const uint4* __restrict__ wpA, const uint4* __restrict__ wpB,
    const float* __restrict__ bsA, const float* __restrict__ bsB,
    const float* __restrict__ skA, const float* __restrict__ skB,
    uint4* __restrict__ yp, int mode)
{
    extern __shared__ u32 smc[];
    u32* Hhi = smc;
    u32* Hlo = smc + 11520;

    const int bz = blockIdx.z;
    const int combo = bz >> 2, b = bz & 3;
    const uint4* xp = ((combo & 1) ? xpB : xpA) + (size_t)combo * xstride_u4;
    const uint4* wp = (combo >> 1) ? wpB : wpA;
    const float* bias = (combo >> 1) ? bsB : bsA;
    const float* skip = (combo & 1) ? skB : skA;

    const int ty = blockIdx.y, tx = blockIdx.x;
    const int tid = threadIdx.x, wid = tid >> 5, lane = tid & 31;
    const int g = lane >> 2, t = lane & 3;

    const int y0 = ty * 16 - 1, x0 = tx * 16 - 1;
    for (int i = tid; i < 324 * 16; i += 256) {
        int pix = i >> 4, j = i & 15;
        int yy = pix / 18, xx = pix - yy * 18;
        int gy = y0 + yy, gx = x0 + xx;
        uint4 v = make_uint4(0u, 0u, 0u, 0u);
        if (gy >= 0 && gy < HH && gx >= 0 && gx < WW)
            v = __ldg(&xp[(size_t)((b * HH + gy) * WW + gx) * 16 + j]);
        int unitoff = (yy * 20 + xx) * 32 + (((j >> 1) ^ (xx & 7)) << 2) + ((j & 1) << 1);
        *(uint2*)&Hhi[unitoff] = make_uint2(v.x, v.z);
        *(uint2*)&Hlo[unitoff] = make_uint2(v.y, v.w);
    }
    __syncthreads();

    float acc[2][8][4];
#pragma unroll
    for (int mi = 0; mi < 2; mi++)
#pragma unroll
        for (int n8 = 0; n8 < 8; n8++)
#pragma unroll
            for (int q = 0; q < 4; q++) acc[mi][n8][q] = 0.f;

    const int row0 = 2 * wid;
    const u32 hbase = (u32)__cvta_generic_to_shared(Hhi);
    const u32 lbase = (u32)__cvta_generic_to_shared(Hlo);
    const int m = lane & 15, half = lane >> 4;

    for (int ch = 0; ch < 4; ch++) {
#pragma unroll
        for (int dx = 0; dx < 3; dx++) {
            const int xm = dx + m;
            const int coff = (((ch * 2 + half) ^ (xm & 7)) << 4);
            const u32 a0 = (u32)((row0 * 20 + xm) * 128 + coff);
            u32 fh[4][4], fl[4][4];
#pragma unroll
            for (int ri = 0; ri < 4; ri++) {
                ldsm4(fh[ri], hbase + a0 + ri * 2560);
                ldsm4(fl[ri], lbase + a0 + ri * 2560);
            }
#pragma unroll
            for (int dy = 0; dy < 3; dy++) {
                const uint4* wrow = wp + (((dy * 3 + dx) * 4 + ch) * 64) * 4 + t;
#pragma unroll
                for (int n8 = 0; n8 < 8; n8++) {
                    uint4 Bv = __ldg(&wrow[(n8 * 8 + g) * 4]);
#pragma unroll
                    for (int mi = 0; mi < 2; mi++) {
                        const int ri = mi + dy;
                        mma16816(acc[mi][n8], fh[ri][0], fh[ri][1], fh[ri][2], fh[ri][3], Bv.x, Bv.y);
                        mma16816(acc[mi][n8], fh[ri][0], fh[ri][1], fh[ri][2], fh[ri][3], Bv.z, Bv.w);
                        mma16816(acc[mi][n8], fl[ri][0], fl[ri][1], fl[ri][2], fl[ri][3], Bv.x, Bv.y);
                    }
                }
            }
        }
    }

    const int gyb = ty * 16 + row0, gxb = tx * 16;
    uint2* ypc = (uint2*)(yp + (size_t)combo * (NPIX * 16));
#pragma unroll
    for (int n8 = 0; n8 < 8; n8++) {
        const int och0 = n8 * 8 + 2 * t;
        const float b0 = __ldg(&bias[och0]);
        const float b1 = __ldg(&bias[och0 + 1]);
        const int c2o = n8 * 4 + t;
#pragma unroll
        for (int mi = 0; mi < 2; mi++) {
            const int gy = gyb + mi;
#pragma unroll
            for (int hlf = 0; hlf < 2; hlf++) {
                const int px = gxb + g + hlf * 8;
                float v0 = acc[mi][n8][hlf * 2 + 0] + b0;
                float v1 = acc[mi][n8][hlf * 2 + 1] + b1;
                if (mode == 1) {
                    v0 = fmaxf(v0, 0.f);
                    v1 = fmaxf(v1, 0.f);
                } else if (mode == 2) {
                    const int off = ((b * 64 + och0) * HH + gy) * WW + px;
                    v0 += __ldg(&skip[off]);
                    v1 += __ldg(&skip[off + CS]);
                }
                u32 h, l;
                split_pack(v0, v1, h, l);
                ypc[(size_t)((b * HH + gy) * WW + px) * 32 + c2o] = make_uint2(h, l);
            }
        }
    }
}

// =================================================================================
// Tensor-core attention. One CTA per (b,h), 384 threads = 12 warps.
// SMEM byte map (198656 total):
//   [0, 73728)       Sh plane: S hi bf16 [w=192][v units 24 x 16B], row 384B,
//                    phys unit = (u&24)|((u&7)^(w&7))   (after S is computed)
//   [73728, 147456)  Sl plane
//   -- before S is written, same region holds Q/K staging:
//   [0, 24576)       Qsh: Q^T hi [w=192][c 8x16B units], row 128B, unit^(w&7)
//   [24576, 49152)   Qsl
//   [49152, 76800)   Kh: [pixel v=192][36 u32] (u32 = channel-pair bf16x2)
//   [76800, 104448)  Kl
//   [147456, 173056) Fh: features [c=64][100 u32] (u32 = v-pair bf16x2)
//   [173056, 198656) Fl
// =================================================================================
#define SH_B   0
#define SL_B   73728
#define QSH_U  0        // u32 indices
#define QSL_U  6144
#define KH_U   12288
#define KL_U   19200
#define FH_U   36864
#define FL_U   43264
#define ATTN_SMEM 198656

__device__ __forceinline__ void stage_qk(u32* sm, const uint4* __restrict__ q,
                                         const uint4* __restrict__ k,
                                         int pixbase, int tid)
{
#pragma unroll
    for (int it = 0; it < 8; it++) {
        int i = tid + it * 384;
        int p = i >> 4, j = i & 15;
        uint4 vq = __ldg(&q[(size_t)(pixbase + p) * 16 + j]);
        uint4 vk = __ldg(&k[(size_t)(pixbase + p) * 16 + j]);
        int us = (j >> 1) ^ (p & 7);
        int qoff = p * 32 + us * 4 + (j & 1) * 2;
        *(uint2*)(sm + QSH_U + qoff) = make_uint2(vq.x, vq.z);
        *(uint2*)(sm + QSL_U + qoff) = make_uint2(vq.y, vq.w);
        int koff = p * 36 + 2 * j;
        *(uint2*)(sm + KH_U + koff) = make_uint2(vk.x, vk.z);
        *(uint2*)(sm + KL_U + koff) = make_uint2(vk.y, vk.w);
    }
}

// S = Q^T K (bf16x3 MMA), softmax rows in registers, store bf16x2 S planes.
__device__ __forceinline__ void compute_store_S(u32* sm, u32 smem_base,
                                                int wid, int lane)
{
    const int g = lane >> 2, t = lane & 3;
    const int w0 = wid * 16;
    const int tile = lane >> 3, lr = lane & 7;
    const int arow = w0 + lr + ((tile & 1) << 3);

    float acc[24][4];
#pragma unroll
    for (int n8 = 0; n8 < 24; n8++)
#pragma unroll
        for (int q = 0; q < 4; q++) acc[n8][q] = 0.f;

    const u32* kh = sm + KH_U;
    const u32* kl = sm + KL_U;

#pragma unroll
    for (int ch = 0; ch < 4; ch++) {
        const int ut = 2 * ch + (tile >> 1);
        const int us = ut ^ (arow & 7);
        const u32 qaddr = smem_base + (u32)(arow * 128 + us * 16);
        u32 ah[4], al[4];
        ldsm4(ah, qaddr);
        ldsm4(al, qaddr + 24576);
        const int kbase = ch * 8 + t;
#pragma unroll
        for (int n8 = 0; n8 < 24; n8++) {
            const int p36 = (n8 * 8 + g) * 36;
            u32 b0h = kh[p36 + kbase], b1h = kh[p36 + kbase + 4];
            u32 b0l = kl[p36 + kbase], b1l = kl[p36 + kbase + 4];
            mma16816(acc[n8], ah[0], ah[1], ah[2], ah[3], b0h, b1h);
            mma16816(acc[n8], ah[0], ah[1], ah[2], ah[3], b0l, b1l);
            mma16816(acc[n8], al[0], al[1], al[2], al[3], b0h, b1h);
        }
    }

    // softmax: lane holds rows rg = w0+g (acc[.][0..1]) and rg+8 (acc[.][2..3])
    float m0 = -1e30f, m1 = -1e30f;
#pragma unroll
    for (int n8 = 0; n8 < 24; n8++) {
        m0 = fmaxf(m0, fmaxf(acc[n8][0], acc[n8][1]));
        m1 = fmaxf(m1, fmaxf(acc[n8][2], acc[n8][3]));
    }
    m0 = fmaxf(m0, __shfl_xor_sync(0xffffffffu, m0, 1));
    m0 = fmaxf(m0, __shfl_xor_sync(0xffffffffu, m0, 2));
    m1 = fmaxf(m1, __shfl_xor_sync(0xffffffffu, m1, 1));
    m1 = fmaxf(m1, __shfl_xor_sync(0xffffffffu, m1, 2));
    float s0 = 0.f, s1 = 0.f;
#pragma unroll
    for (int n8 = 0; n8 < 24; n8++) {
        acc[n8][0] = __expf(acc[n8][0] - m0);
        acc[n8][1] = __expf(acc[n8][1] - m0);
        acc[n8][2] = __expf(acc[n8][2] - m1);
        acc[n8][3] = __expf(acc[n8][3] - m1);
        s0 += acc[n8][0] + acc[n8][1];
        s1 += acc[n8][2] + acc[n8][3];
    }
    s0 += __shfl_xor_sync(0xffffffffu, s0, 1);
    s0 += __shfl_xor_sync(0xffffffffu, s0, 2);
    s1 += __shfl_xor_sync(0xffffffffu, s1, 1);
    s1 += __shfl_xor_sync(0xffffffffu, s1, 2);
    const float inv0 = 1.0f / s0, inv1 = 1.0f / s1;

    __syncthreads();   // all warps done reading Qs/Ks before S overwrites them

    u32* shp = sm;                    // Sh as u32, row stride 96
    u32* slp = sm + SL_B / 4;
    const int rg = w0 + g;
#pragma unroll
    for (int n8 = 0; n8 < 24; n8++) {
        const int us = (n8 & 24) | ((n8 & 7) ^ (rg & 7));   // (rg+8)&7 == rg&7
        const int off = us * 4 + t;
        u32 h, l;
        split_pack(acc[n8][0] * inv0, acc[n8][1] * inv0, h, l);
        shp[rg * 96 + off] = h;
        slp[rg * 96 + off] = l;
        split_pack(acc[n8][2] * inv1, acc[n8][3] * inv1, h, l);
        shp[(rg + 8) * 96 + off] = h;
        slp[(rg + 8) * 96 + off] = l;
    }
}

// fp32 NCHW feature row -> Fh/Fl v-pair-packed [c][100]
__device__ __forceinline__ void load_F(u32* sm, const float* __restrict__ src,
                                       int rb, int tid)
{
#pragma unroll
    for (int it = 0; it < 8; it++) {
        int i = tid + it * 384;
        int c = i / 48, q = i - c * 48;
        float4 f = *(const float4*)(src + rb + c * CS + q * 4);
        u32 h0, l0, h1, l1;
        split_pack(f.x, f.y, h0, l0);
        split_pack(f.z, f.w, h1, l1);
        *(uint2*)(sm + FH_U + c * 100 + 2 * q) = make_uint2(h0, h1);
        *(uint2*)(sm + FL_U + c * 100 + 2 * q) = make_uint2(l0, l1);
    }
}

// D[w][c] = sum_v S'[w][v] * feat[c][v]; S' = S (TR=0) or S^T (TR=1)
template <bool TR>
__device__ __forceinline__ void apply_tc(u32* sm, u32 smem_base,
                                         int wid, int lane, float acc[8][4])
{
    const int g = lane >> 2, t = lane & 3;
    const int w0 = wid * 16;
    const int tile = lane >> 3, lr = lane & 7;
    const u32* fh = sm + FH_U;
    const u32* fl = sm + FL_U;

#pragma unroll
    for (int n8 = 0; n8 < 8; n8++)
#pragma unroll
        for (int q = 0; q < 4; q++) acc[n8][q] = 0.f;

#pragma unroll
    for (int k = 0; k < 12; k++) {
        u32 ah[4], al[4];
        if (!TR) {
            const int row = w0 + lr + ((tile & 1) << 3);
            const int ut = 2 * k + (tile >> 1);
            const int us = (ut & 24) | ((ut & 7) ^ (row & 7));
            const u32 addr = smem_base + (u32)(row * 384 + us * 16);
            ldsm4(ah, addr);
            ldsm4(al, addr + 73728);
        } else {
            const int srow = k * 16 + lr + ((tile >> 1) << 3);
            const int cu = 2 * wid + (tile & 1);
            const int us = (cu & 24) | ((cu & 7) ^ (srow & 7));
            const u32 addr = smem_base + (u32)(srow * 384 + us * 16);
            ldsm4t(ah, addr);
            ldsm4t(al, addr + 73728);
        }
        const int fb = 8 * k + t;
#pragma unroll
        for (int n8 = 0; n8 < 8; n8++) {
            const int c100 = (n8 * 8 + g) * 100;
            u32 b0h = fh[c100 + fb], b1h = fh[c100 + fb + 4];
            u32 b0l = fl[c100 + fb], b1l = fl[c100 + fb + 4];
            mma16816(acc[n8], ah[0], ah[1], ah[2], ah[3], b0h, b1h);
            mma16816(acc[n8], ah[0], ah[1], ah[2], ah[3], b0l, b1l);
            mma16816(acc[n8], al[0], al[1], al[2], al[3], b0h, b1h);
        }
    }
}

__device__ __forceinline__ void emit_init2(float* dst, float* scratch,
                                           const float* base, const float acc[8][4],
                                           int rb, int wid, int lane)
{
    const int g = lane >> 2, t = lane & 3, w0 = wid * 16;
#pragma unroll
    for (int n8 = 0; n8 < 8; n8++)
#pragma unroll
        for (int q = 0; q < 4; q++) {
            const int c = n8 * 8 + 2 * t + (q & 1);
            const int w = w0 + g + ((q >> 1) << 3);
            const int off = rb + c * CS + w;
            const float v = acc[n8][q];
            scratch[off] = v;
            dst[off] = base[off] + v;
        }
}

__device__ __forceinline__ void emit_add2(float* dst, const float acc[8][4],
                                          int rb, int wid, int lane)
{
    const int g = lane >> 2, t = lane & 3, w0 = wid * 16;
#pragma unroll
    for (int n8 = 0; n8 < 8; n8++)
#pragma unroll
        for (int q = 0; q < 4; q++) {
            const int c = n8 * 8 + 2 * t + (q & 1);
            const int w = w0 + g + ((q >> 1) << 3);
            dst[rb + c * CS + w] += acc[n8][q];
        }
}

__global__ void __launch_bounds__(384, 1) attn_tc(
    const float* __restrict__ low1, const float* __restrict__ low2,
    const uint4* __restrict__ qkp,
    float* __restrict__ r2l1s, float* __restrict__ l2r1s,
    float* __restrict__ outL, float* __restrict__ outR)
{
    extern __shared__ u32 sm[];
    const int h = blockIdx.x, b = blockIdx.y;
    const int tid = threadIdx.x, wid = tid >> 5, lane = tid & 31;
    const int rb = b * 64 * CS + h * WW;
    const int pixbase = (b * HH + h) * WW;
    const u32 smem_base = (u32)__cvta_generic_to_shared(sm);
    float acc[8][4];

    // ---- stage 1: S1 = softmax(Q1^T K1) ----
    stage_qk(sm, qkp + 0, qkp + (size_t)1 * NPIX * 16, pixbase, tid);
    __syncthreads();
    compute_store_S(sm, smem_base, wid, lane);   // internal sync before S store
    __syncthreads();

    load_F(sm, low2, rb, tid); __syncthreads();
    apply_tc<false>(sm, smem_base, wid, lane, acc);
    emit_init2(outL, r2l1s, low1, acc, rb, wid, lane);
    __syncthreads();

    load_F(sm, low1, rb, tid); __syncthreads();
    apply_tc<true>(sm, smem_base, wid, lane, acc);
    emit_init2(outR, l2r1s, low2, acc, rb, wid, lane);
    __syncthreads();

    // ---- stage 2: S2 = softmax(Q2^T K2) ----
    stage_qk(sm, qkp + (size_t)2 * NPIX * 16, qkp + (size_t)3 * NPIX * 16,
             pixbase, tid);
    __syncthreads();
    compute_store_S(sm, smem_base, wid, lane);
    __syncthreads();

    load_F(sm, low2, rb, tid); __syncthreads();
    apply_tc<false>(sm, smem_base, wid, lane, acc);
    emit_add2(outL, acc, rb, wid, lane);
    __syncthreads();

    load_F(sm, low1, rb, tid); __syncthreads();
    apply_tc<true>(sm, smem_base, wid, lane, acc);
    emit_add2(outR, acc, rb, wid, lane);
    __syncthreads();

    load_F(sm, l2r1s, rb, tid); __syncthreads();
    apply_tc<false>(sm, smem_base, wid, lane, acc);
    emit_add2(outL, acc, rb, wid, lane);
    __syncthreads();

    load_F(sm, r2l1s, rb, tid); __syncthreads();
    apply_tc<true>(sm, smem_base, wid, lane, acc);
    emit_add2(outR, acc, rb, wid, lane);
}

// =================================================================================
extern "C" void kernel_launch(void* const* d_in, const int* in_sizes, int n_in,
                              void* d_out, int out_size)
{
    const float* low1   = (const float*)d_in[0];
    const float* low2   = (const float*)d_in[1];
    const float* fe1_w1 = (const float*)d_in[2];
    const float* fe1_b1 = (const float*)d_in[3];
    const float* fe1_w2 = (const float*)d_in[4];
    const float* fe1_b2 = (const float*)d_in[5];
    const float* fe2_w1 = (const float*)d_in[6];
    const float* fe2_b1 = (const float*)d_in[7];
    const float* fe2_w2 = (const float*)d_in[8];
    const float* fe2_b2 = (const float*)d_in[9];
    const float* conv_w = (const float*)d_in[10];
    const float* conv_b = (const float*)d_in[11];
    float* out = (float*)d_out;

    uint4 *low1p, *low2p, *tp, *ap, *qkp, *wp;
    float *r2l1, *l2r1;
    cudaGetSymbolAddress((void**)&low1p, g_low1p);
    cudaGetSymbolAddress((void**)&low2p, g_low2p);
    cudaGetSymbolAddress((void**)&tp,    g_tp);
    cudaGetSymbolAddress((void**)&ap,    g_ap);
    cudaGetSymbolAddress((void**)&qkp,   g_qkp);
    cudaGetSymbolAddress((void**)&wp,    g_wp);
    cudaGetSymbolAddress((void**)&r2l1,  g_r2l1);
    cudaGetSymbolAddress((void**)&l2r1,  g_l2r1);

    uint4* wp_fe1w1 = wp + 0 * 9216;
    uint4* wp_fe2w1 = wp + 1 * 9216;
    uint4* wp_fe1w2 = wp + 2 * 9216;
    uint4* wp_fe2w2 = wp + 3 * 9216;
    uint4* wp_convw = wp + 4 * 9216;

    cudaFuncSetAttribute(conv3x3_tc,
                         cudaFuncAttributeMaxDynamicSharedMemorySize,
                         CONV_SMEM_BYTES);
    cudaFuncSetAttribute(attn_tc,
                         cudaFuncAttributeMaxDynamicSharedMemorySize, ATTN_SMEM);

    const dim3 cgrid(WW / 16, HH / 16, 4 * BB);

    pack_weights_all<<<180, 256>>>(fe1_w1, fe2_w1, fe1_w2, fe2_w2, conv_w, wp);
    pack_features_all<<<(2 * 16 * NPIX + 255) / 256, 256>>>(low1, low2, low1p, low2p);

    conv3x3_tc<<<cgrid, 256, CONV_SMEM_BYTES>>>(
        low1p, low2p, 0, wp_fe1w1, wp_fe2w1, fe1_b1, fe2_b1,
        nullptr, nullptr, tp, 1);
    conv3x3_tc<<<cgrid, 256, CONV_SMEM_BYTES>>>(
        tp, tp, NPIX * 16, wp_fe1w2, wp_fe2w2, fe1_b2, fe2_b2,
        low1, low2, ap, 2);
    conv3x3_tc<<<cgrid, 256, CONV_SMEM_BYTES>>>(
        ap, ap, NPIX * 16, wp_convw, wp_convw, conv_b, conv_b,
        nullptr, nullptr, qkp, 3);

    attn_tc<<<dim3(HH, BB), 384, ATTN_SMEM>>>(
        low1, low2, qkp, r2l1, l2r1, out, out + NT);
}

// round 9
// speedup vs baseline: 1.8306x; 1.0520x over previous
#include <cuda_runtime.h>
#include <cuda_bf16.h>

typedef unsigned int u32;
typedef unsigned long long u64;

// Problem constants
#define BB 4
#define CC 64
#define HH 192
#define WW 192
#define CS (HH*WW)            // channel stride = 36864
#define NT (BB*CC*HH*WW)      // elems per [B,C,H,W] fp32 tensor
#define NPIX (BB*HH*WW)       // pixels per tensor = 147456

// ---------------- static scratch (no runtime allocation allowed) ----------------
__device__ uint4 g_low1p[NPIX * 16];
__device__ uint4 g_low2p[NPIX * 16];
__device__ uint4 g_tp[4 * NPIX * 16];   // packed conv1 outputs, per combo
__device__ uint4 g_ap[4 * NPIX * 16];   // packed conv2 outputs, per combo
__device__ uint4 g_qkp[4 * NPIX * 16];  // packed conv3 outputs: Q1,K1,Q2,K2
__device__ uint4 g_wp[5][9216];         // prepacked weights
__device__ float g_r2l1[NT];
__device__ float g_l2r1[NT];

// ---------------- helpers ----------------
__device__ __forceinline__ void split_pack(float ev, float ov, u32 &hi, u32 &lo)
{
    __nv_bfloat16 eh = __float2bfloat16(ev);
    __nv_bfloat16 oh = __float2bfloat16(ov);
    __nv_bfloat16 el = __float2bfloat16(ev - __bfloat162float(eh));
    __nv_bfloat16 ol = __float2bfloat16(ov - __bfloat162float(oh));
    hi = (u32)__bfloat16_as_ushort(eh) | ((u32)__bfloat16_as_ushort(oh) << 16);
    lo = (u32)__bfloat16_as_ushort(el) | ((u32)__bfloat16_as_ushort(ol) << 16);
}

__device__ __forceinline__ void mma16816(float c[4],
                                         u32 a0, u32 a1, u32 a2, u32 a3,
                                         u32 b0, u32 b1)
{
    asm volatile(
        "mma.sync.aligned.m16n8k16.row.col.f32.bf16.bf16.f32 "
        "{%0,%1,%2,%3}, {%4,%5,%6,%7}, {%8,%9}, {%0,%1,%2,%3};"
        : "+f"(c[0]), "+f"(c[1]), "+f"(c[2]), "+f"(c[3])
        : "r"(a0), "r"(a1), "r"(a2), "r"(a3), "r"(b0), "r"(b1));
}

__device__ __forceinline__ void ldsm4(u32 f[4], u32 addr)
{
    asm volatile(
        "ldmatrix.sync.aligned.m8n8.x4.shared.b16 {%0,%1,%2,%3}, [%4];"
        : "=r"(f[0]), "=r"(f[1]), "=r"(f[2]), "=r"(f[3]) : "r"(addr));
}

__device__ __forceinline__ void ldsm4t(u32 f[4], u32 addr)
{
    asm volatile(
        "ldmatrix.sync.aligned.m8n8.x4.trans.shared.b16 {%0,%1,%2,%3}, [%4];"
        : "=r"(f[0]), "=r"(f[1]), "=r"(f[2]), "=r"(f[3]) : "r"(addr));
}

// =================================================================================
// Prep kernels (one launch each)
// =================================================================================
__global__ void pack_weights_all(
    const float* __restrict__ w0, const float* __restrict__ w1,
    const float* __restrict__ w2, const float* __restrict__ w3,
    const float* __restrict__ w4, uint4* __restrict__ wp)
{
    int idx = blockIdx.x * 256 + threadIdx.x;
    if (idx >= 5 * 9216) return;
    int which = idx / 9216, r = idx % 9216;
    const float* w = (which == 0) ? w0 : (which == 1) ? w1 :
                     (which == 2) ? w2 : (which == 3) ? w3 : w4;
    int tap = r >> 10, rem = r & 1023;
    int chunk = rem >> 8, rem2 = rem & 255;
    int o = rem2 >> 2, t = rem2 & 3;
    int c2a = chunk * 8 + t, c2b = c2a + 4;
    u32 h0, l0, h1, l1;
    split_pack(__ldg(&w[o * 576 + (2 * c2a) * 9 + tap]),
               __ldg(&w[o * 576 + (2 * c2a + 1) * 9 + tap]), h0, l0);
    split_pack(__ldg(&w[o * 576 + (2 * c2b) * 9 + tap]),
               __ldg(&w[o * 576 + (2 * c2b + 1) * 9 + tap]), h1, l1);
    wp[idx] = make_uint4(h0, h1, l0, l1);
}

__global__ void pack_features_all(const float* __restrict__ x1,
                                  const float* __restrict__ x2,
                                  uint4* __restrict__ xp1,
                                  uint4* __restrict__ xp2)
{
    int gi = blockIdx.x * 256 + threadIdx.x;
    if (gi >= 2 * 16 * NPIX) return;
    int tsel = gi / (16 * NPIX);
    int r = gi - tsel * 16 * NPIX;
    int j = r / NPIX;
    int p = r - j * NPIX;
    const float* x = tsel ? x2 : x1;
    uint4* xp = tsel ? xp2 : xp1;
    int b = p / (HH * WW);
    int pos = p - b * HH * WW;
    const float* src = x + (size_t)(b * 64 + 4 * j) * CS + pos;
    u32 h0, l0, h1, l1;
    split_pack(src[0], src[CS], h0, l0);
    split_pack(src[2 * CS], src[3 * CS], h1, l1);
    xp[(size_t)p * 16 + j] = make_uint4(h0, l0, h1, l1);
}

// =================================================================================
// Tensor-core conv 3x3 (R6 design). mode 1: relu->packed; mode 2: +skip->packed;
// mode 3: bias only->packed (Q/K for attention).
// =================================================================================
#define CONV_SMEM_BYTES (23040*4)

__global__ void __launch_bounds__(256, 2) conv3x3_tc(
    const uint4* __restrict__ xpA, const uint4* __restrict__ xpB, int xstride_u4,
    const uint4* __restrict__ wpA, const uint4* __restrict__ wpB,
    const float* __restrict__ bsA, const float* __restrict__ bsB,
    const float* __restrict__ skA, const float* __restrict__ skB,
    uint4* __restrict__ yp, int mode)
{
    extern __shared__ u32 smc[];
    u32* Hhi = smc;
    u32* Hlo = smc + 11520;

    const int bz = blockIdx.z;
    const int combo = bz >> 2, b = bz & 3;
    const uint4* xp = ((combo & 1) ? xpB : xpA) + (size_t)combo * xstride_u4;
    const uint4* wp = (combo >> 1) ? wpB : wpA;
    const float* bias = (combo >> 1) ? bsB : bsA;
    const float* skip = (combo & 1) ? skB : skA;

    const int ty = blockIdx.y, tx = blockIdx.x;
    const int tid = threadIdx.x, wid = tid >> 5, lane = tid & 31;
    const int g = lane >> 2, t = lane & 3;

    const int y0 = ty * 16 - 1, x0 = tx * 16 - 1;
    for (int i = tid; i < 324 * 16; i += 256) {
        int pix = i >> 4, j = i & 15;
        int yy = pix / 18, xx = pix - yy * 18;
        int gy = y0 + yy, gx = x0 + xx;
        uint4 v = make_uint4(0u, 0u, 0u, 0u);
        if (gy >= 0 && gy < HH && gx >= 0 && gx < WW)
            v = __ldg(&xp[(size_t)((b * HH + gy) * WW + gx) * 16 + j]);
        int unitoff = (yy * 20 + xx) * 32 + (((j >> 1) ^ (xx & 7)) << 2) + ((j & 1) << 1);
        *(uint2*)&Hhi[unitoff] = make_uint2(v.x, v.z);
        *(uint2*)&Hlo[unitoff] = make_uint2(v.y, v.w);
    }
    __syncthreads();

    float acc[2][8][4];
#pragma unroll
    for (int mi = 0; mi < 2; mi++)
#pragma unroll
        for (int n8 = 0; n8 < 8; n8++)
#pragma unroll
            for (int q = 0; q < 4; q++) acc[mi][n8][q] = 0.f;

    const int row0 = 2 * wid;
    const u32 hbase = (u32)__cvta_generic_to_shared(Hhi);
    const u32 lbase = (u32)__cvta_generic_to_shared(Hlo);
    const int m = lane & 15, half = lane >> 4;

    for (int ch = 0; ch < 4; ch++) {
#pragma unroll
        for (int dx = 0; dx < 3; dx++) {
            const int xm = dx + m;
            const int coff = (((ch * 2 + half) ^ (xm & 7)) << 4);
            const u32 a0 = (u32)((row0 * 20 + xm) * 128 + coff);
            u32 fh[4][4], fl[4][4];
#pragma unroll
            for (int ri = 0; ri < 4; ri++) {
                ldsm4(fh[ri], hbase + a0 + ri * 2560);
                ldsm4(fl[ri], lbase + a0 + ri * 2560);
            }
#pragma unroll
            for (int dy = 0; dy < 3; dy++) {
                const uint4* wrow = wp + (((dy * 3 + dx) * 4 + ch) * 64) * 4 + t;
#pragma unroll
                for (int n8 = 0; n8 < 8; n8++) {
                    uint4 Bv = __ldg(&wrow[(n8 * 8 + g) * 4]);
#pragma unroll
                    for (int mi = 0; mi < 2; mi++) {
                        const int ri = mi + dy;
                        mma16816(acc[mi][n8], fh[ri][0], fh[ri][1], fh[ri][2], fh[ri][3], Bv.x, Bv.y);
                        mma16816(acc[mi][n8], fh[ri][0], fh[ri][1], fh[ri][2], fh[ri][3], Bv.z, Bv.w);
                        mma16816(acc[mi][n8], fl[ri][0], fl[ri][1], fl[ri][2], fl[ri][3], Bv.x, Bv.y);
                    }
                }
            }
        }
    }

    const int gyb = ty * 16 + row0, gxb = tx * 16;
    uint2* ypc = (uint2*)(yp + (size_t)combo * (NPIX * 16));
#pragma unroll
    for (int n8 = 0; n8 < 8; n8++) {
        const int och0 = n8 * 8 + 2 * t;
        const float b0 = __ldg(&bias[och0]);
        const float b1 = __ldg(&bias[och0 + 1]);
        const int c2o = n8 * 4 + t;
#pragma unroll
        for (int mi = 0; mi < 2; mi++) {
            const int gy = gyb + mi;
#pragma unroll
            for (int hlf = 0; hlf < 2; hlf++) {
                const int px = gxb + g + hlf * 8;
                float v0 = acc[mi][n8][hlf * 2 + 0] + b0;
                float v1 = acc[mi][n8][hlf * 2 + 1] + b1;
                if (mode == 1) {
                    v0 = fmaxf(v0, 0.f);
                    v1 = fmaxf(v1, 0.f);
                } else if (mode == 2) {
                    const int off = ((b * 64 + och0) * HH + gy) * WW + px;
                    v0 += __ldg(&skip[off]);
                    v1 += __ldg(&skip[off + CS]);
                }
                u32 h, l;
                split_pack(v0, v1, h, l);
                ypc[(size_t)((b * HH + gy) * WW + px) * 32 + c2o] = make_uint2(h, l);
            }
        }
    }
}

// =================================================================================
// Tensor-core attention. One CTA per (b,h), 384 threads = 12 warps.
// 6 MMA phases (stage-2 applies fused by linearity:
//   outL += S2 @ (low2 + l2r1),  outR += S2^T @ (low1 + r2l1) ).
// SMEM byte map (198656 total): see R8 layout comments.
// =================================================================================
#define SH_B   0
#define SL_B   73728
#define QSH_U  0        // u32 indices
#define QSL_U  6144
#define KH_U   12288
#define KL_U   19200
#define FH_U   36864
#define FL_U   43264
#define ATTN_SMEM 198656

__device__ __forceinline__ void stage_qk(u32* sm, const uint4* __restrict__ q,
                                         const uint4* __restrict__ k,
                                         int pixbase, int tid)
{
#pragma unroll
    for (int it = 0; it < 8; it++) {
        int i = tid + it * 384;
        int p = i >> 4, j = i & 15;
        uint4 vq = __ldg(&q[(size_t)(pixbase + p) * 16 + j]);
        uint4 vk = __ldg(&k[(size_t)(pixbase + p) * 16 + j]);
        int us = (j >> 1) ^ (p & 7);
        int qoff = p * 32 + us * 4 + (j & 1) * 2;
        *(uint2*)(sm + QSH_U + qoff) = make_uint2(vq.x, vq.z);
        *(uint2*)(sm + QSL_U + qoff) = make_uint2(vq.y, vq.w);
        int koff = p * 36 + 2 * j;
        *(uint2*)(sm + KH_U + koff) = make_uint2(vk.x, vk.z);
        *(uint2*)(sm + KL_U + koff) = make_uint2(vk.y, vk.w);
    }
}

// S = Q^T K (bf16x3 MMA), softmax rows in registers, store bf16x2 S planes.
__device__ __forceinline__ void compute_store_S(u32* sm, u32 smem_base,
                                                int wid, int lane)
{
    const int g = lane >> 2, t = lane & 3;
    const int w0 = wid * 16;
    const int tile = lane >> 3, lr = lane & 7;
    const int arow = w0 + lr + ((tile & 1) << 3);

    float acc[24][4];
#pragma unroll
    for (int n8 = 0; n8 < 24; n8++)
#pragma unroll
        for (int q = 0; q < 4; q++) acc[n8][q] = 0.f;

    const u32* kh = sm + KH_U;
    const u32* kl = sm + KL_U;

#pragma unroll
    for (int ch = 0; ch < 4; ch++) {
        const int ut = 2 * ch + (tile >> 1);
        const int us = ut ^ (arow & 7);
        const u32 qaddr = smem_base + (u32)(arow * 128 + us * 16);
        u32 ah[4], al[4];
        ldsm4(ah, qaddr);
        ldsm4(al, qaddr + 24576);
        const int kbase = ch * 8 + t;
#pragma unroll
        for (int n8 = 0; n8 < 24; n8++) {
            const int p36 = (n8 * 8 + g) * 36;
            u32 b0h = kh[p36 + kbase], b1h = kh[p36 + kbase + 4];
            u32 b0l = kl[p36 + kbase], b1l = kl[p36 + kbase + 4];
            mma16816(acc[n8], ah[0], ah[1], ah[2], ah[3], b0h, b1h);
            mma16816(acc[n8], ah[0], ah[1], ah[2], ah[3], b0l, b1l);
            mma16816(acc[n8], al[0], al[1], al[2], al[3], b0h, b1h);
        }
    }

    float m0 = -1e30f, m1 = -1e30f;
#pragma unroll
    for (int n8 = 0; n8 < 24; n8++) {
        m0 = fmaxf(m0, fmaxf(acc[n8][0], acc[n8][1]));
        m1 = fmaxf(m1, fmaxf(acc[n8][2], acc[n8][3]));
    }
    m0 = fmaxf(m0, __shfl_xor_sync(0xffffffffu, m0, 1));
    m0 = fmaxf(m0, __shfl_xor_sync(0xffffffffu, m0, 2));
    m1 = fmaxf(m1, __shfl_xor_sync(0xffffffffu, m1, 1));
    m1 = fmaxf(m1, __shfl_xor_sync(0xffffffffu, m1, 2));
    float s0 = 0.f, s1 = 0.f;
#pragma unroll
    for (int n8 = 0; n8 < 24; n8++) {
        acc[n8][0] = __expf(acc[n8][0] - m0);
        acc[n8][1] = __expf(acc[n8][1] - m0);
        acc[n8][2] = __expf(acc[n8][2] - m1);
        acc[n8][3] = __expf(acc[n8][3] - m1);
        s0 += acc[n8][0] + acc[n8][1];
        s1 += acc[n8][2] + acc[n8][3];
    }
    s0 += __shfl_xor_sync(0xffffffffu, s0, 1);
    s0 += __shfl_xor_sync(0xffffffffu, s0, 2);
    s1 += __shfl_xor_sync(0xffffffffu, s1, 1);
    s1 += __shfl_xor_sync(0xffffffffu, s1, 2);
    const float inv0 = 1.0f / s0, inv1 = 1.0f / s1;

    __syncthreads();   // all warps done reading Qs/Ks before S overwrites them

    u32* shp = sm;                    // Sh as u32, row stride 96
    u32* slp = sm + SL_B / 4;
    const int rg = w0 + g;
#pragma unroll
    for (int n8 = 0; n8 < 24; n8++) {
        const int us = (n8 & 24) | ((n8 & 7) ^ (rg & 7));
        const int off = us * 4 + t;
        u32 h, l;
        split_pack(acc[n8][0] * inv0, acc[n8][1] * inv0, h, l);
        shp[rg * 96 + off] = h;
        slp[rg * 96 + off] = l;
        split_pack(acc[n8][2] * inv1, acc[n8][3] * inv1, h, l);
        shp[(rg + 8) * 96 + off] = h;
        slp[(rg + 8) * 96 + off] = l;
    }
}

// fp32 NCHW feature row -> Fh/Fl v-pair-packed [c][100]
__device__ __forceinline__ void load_F(u32* sm, const float* __restrict__ src,
                                       int rb, int tid)
{
#pragma unroll
    for (int it = 0; it < 8; it++) {
        int i = tid + it * 384;
        int c = i / 48, q = i - c * 48;
        float4 f = *(const float4*)(src + rb + c * CS + q * 4);
        u32 h0, l0, h1, l1;
        split_pack(f.x, f.y, h0, l0);
        split_pack(f.z, f.w, h1, l1);
        *(uint2*)(sm + FH_U + c * 100 + 2 * q) = make_uint2(h0, h1);
        *(uint2*)(sm + FL_U + c * 100 + 2 * q) = make_uint2(l0, l1);
    }
}

// two-source sum variant: packs (srcA + srcB) — linearity fusion for stage 2
__device__ __forceinline__ void load_F2(u32* sm, const float* __restrict__ srcA,
                                        const float* __restrict__ srcB,
                                        int rb, int tid)
{
#pragma unroll
    for (int it = 0; it < 8; it++) {
        int i = tid + it * 384;
        int c = i / 48, q = i - c * 48;
        float4 fa = *(const float4*)(srcA + rb + c * CS + q * 4);
        float4 fb = *(const float4*)(srcB + rb + c * CS + q * 4);
        float4 f = make_float4(fa.x + fb.x, fa.y + fb.y, fa.z + fb.z, fa.w + fb.w);
        u32 h0, l0, h1, l1;
        split_pack(f.x, f.y, h0, l0);
        split_pack(f.z, f.w, h1, l1);
        *(uint2*)(sm + FH_U + c * 100 + 2 * q) = make_uint2(h0, h1);
        *(uint2*)(sm + FL_U + c * 100 + 2 * q) = make_uint2(l0, l1);
    }
}

// D[w][c] = sum_v S'[w][v] * feat[c][v]; S' = S (TR=0) or S^T (TR=1)
template <bool TR>
__device__ __forceinline__ void apply_tc(u32* sm, u32 smem_base,
                                         int wid, int lane, float acc[8][4])
{
    const int g = lane >> 2, t = lane & 3;
    const int w0 = wid * 16;
    const int tile = lane >> 3, lr = lane & 7;
    const u32* fh = sm + FH_U;
    const u32* fl = sm + FL_U;

#pragma unroll
    for (int n8 = 0; n8 < 8; n8++)
#pragma unroll
        for (int q = 0; q < 4; q++) acc[n8][q] = 0.f;

#pragma unroll
    for (int k = 0; k < 12; k++) {
        u32 ah[4], al[4];
        if (!TR) {
            const int row = w0 + lr + ((tile & 1) << 3);
            const int ut = 2 * k + (tile >> 1);
            const int us = (ut & 24) | ((ut & 7) ^ (row & 7));
            const u32 addr = smem_base + (u32)(row * 384 + us * 16);
            ldsm4(ah, addr);
            ldsm4(al, addr + 73728);
        } else {
            const int srow = k * 16 + lr + ((tile >> 1) << 3);
            const int cu = 2 * wid + (tile & 1);
            const int us = (cu & 24) | ((cu & 7) ^ (srow & 7));
            const u32 addr = smem_base + (u32)(srow * 384 + us * 16);
            ldsm4t(ah, addr);
            ldsm4t(al, addr + 73728);
        }
        const int fb = 8 * k + t;
#pragma unroll
        for (int n8 = 0; n8 < 8; n8++) {
            const int c100 = (n8 * 8 + g) * 100;
            u32 b0h = fh[c100 + fb], b1h = fh[c100 + fb + 4];
            u32 b0l = fl[c100 + fb], b1l = fl[c100 + fb + 4];
            mma16816(acc[n8], ah[0], ah[1], ah[2], ah[3], b0h, b1h);
            mma16816(acc[n8], ah[0], ah[1], ah[2], ah[3], b0l, b1l);
            mma16816(acc[n8], al[0], al[1], al[2], al[3], b0h, b1h);
        }
    }
}

__device__ __forceinline__ void emit_init2(float* dst, float* scratch,
                                           const float* base, const float acc[8][4],
                                           int rb, int wid, int lane)
{
    const int g = lane >> 2, t = lane & 3, w0 = wid * 16;
#pragma unroll
    for (int n8 = 0; n8 < 8; n8++)
#pragma unroll
        for (int q = 0; q < 4; q++) {
            const int c = n8 * 8 + 2 * t + (q & 1);
            const int w = w0 + g + ((q >> 1) << 3);
            const int off = rb + c * CS + w;
            const float v = acc[n8][q];
            scratch[off] = v;
            dst[off] = base[off] + v;
        }
}

__device__ __forceinline__ void emit_add2(float* dst, const float acc[8][4],
                                          int rb, int wid, int lane)
{
    const int g = lane >> 2, t = lane & 3, w0 = wid * 16;
#pragma unroll
    for (int n8 = 0; n8 < 8; n8++)
#pragma unroll
        for (int q = 0; q < 4; q++) {
            const int c = n8 * 8 + 2 * t + (q & 1);
            const int w = w0 + g + ((q >> 1) << 3);
            dst[rb + c * CS + w] += acc[n8][q];
        }
}

__global__ void __launch_bounds__(384, 1) attn_tc(
    const float* __restrict__ low1, const float* __restrict__ low2,
    const uint4* __restrict__ qkp,
    float* __restrict__ r2l1s, float* __restrict__ l2r1s,
    float* __restrict__ outL, float* __restrict__ outR)
{
    extern __shared__ u32 sm[];
    const int h = blockIdx.x, b = blockIdx.y;
    const int tid = threadIdx.x, wid = tid >> 5, lane = tid & 31;
    const int rb = b * 64 * CS + h * WW;
    const int pixbase = (b * HH + h) * WW;
    const u32 smem_base = (u32)__cvta_generic_to_shared(sm);
    float acc[8][4];

    // ---- stage 1: S1 = softmax(Q1^T K1) ----
    stage_qk(sm, qkp + 0, qkp + (size_t)1 * NPIX * 16, pixbase, tid);
    __syncthreads();
    compute_store_S(sm, smem_base, wid, lane);   // internal sync before S store
    __syncthreads();

    // r2l1 = S1 @ low2 -> outL (+low1), scratch
    load_F(sm, low2, rb, tid); __syncthreads();
    apply_tc<false>(sm, smem_base, wid, lane, acc);
    emit_init2(outL, r2l1s, low1, acc, rb, wid, lane);
    __syncthreads();

    // l2r1 = S1^T @ low1 -> outR (+low2), scratch
    load_F(sm, low1, rb, tid); __syncthreads();
    apply_tc<true>(sm, smem_base, wid, lane, acc);
    emit_init2(outR, l2r1s, low2, acc, rb, wid, lane);
    __syncthreads();

    // ---- stage 2: S2 = softmax(Q2^T K2) ----
    stage_qk(sm, qkp + (size_t)2 * NPIX * 16, qkp + (size_t)3 * NPIX * 16,
             pixbase, tid);
    __syncthreads();
    compute_store_S(sm, smem_base, wid, lane);
    __syncthreads();

    // outL += S2 @ (low2 + l2r1)   [fused: r2l2 + l2r2l]
    load_F2(sm, low2, l2r1s, rb, tid); __syncthreads();
    apply_tc<false>(sm, smem_base, wid, lane, acc);
    emit_add2(outL, acc, rb, wid, lane);
    __syncthreads();

    // outR += S2^T @ (low1 + r2l1) [fused: l2r2 + r2l2r]
    load_F2(sm, low1, r2l1s, rb, tid); __syncthreads();
    apply_tc<true>(sm, smem_base, wid, lane, acc);
    emit_add2(outR, acc, rb, wid, lane);
}

// =================================================================================
extern "C" void kernel_launch(void* const* d_in, const int* in_sizes, int n_in,
                              void* d_out, int out_size)
{
    const float* low1   = (const float*)d_in[0];
    const float* low2   = (const float*)d_in[1];
    const float* fe1_w1 = (const float*)d_in[2];
    const float* fe1_b1 = (const float*)d_in[3];
    const float* fe1_w2 = (const float*)d_in[4];
    const float* fe1_b2 = (const float*)d_in[5];
    const float* fe2_w1 = (const float*)d_in[6];
    const float* fe2_b1 = (const float*)d_in[7];
    const float* fe2_w2 = (const float*)d_in[8];
    const float* fe2_b2 = (const float*)d_in[9];
    const float* conv_w = (const float*)d_in[10];
    const float* conv_b = (const float*)d_in[11];
    float* out = (float*)d_out;

    uint4 *low1p, *low2p, *tp, *ap, *qkp, *wp;
    float *r2l1, *l2r1;
    cudaGetSymbolAddress((void**)&low1p, g_low1p);
    cudaGetSymbolAddress((void**)&low2p, g_low2p);
    cudaGetSymbolAddress((void**)&tp,    g_tp);
    cudaGetSymbolAddress((void**)&ap,    g_ap);
    cudaGetSymbolAddress((void**)&qkp,   g_qkp);
    cudaGetSymbolAddress((void**)&wp,    g_wp);
    cudaGetSymbolAddress((void**)&r2l1,  g_r2l1);
    cudaGetSymbolAddress((void**)&l2r1,  g_l2r1);

    uint4* wp_fe1w1 = wp + 0 * 9216;
    uint4* wp_fe2w1 = wp + 1 * 9216;
    uint4* wp_fe1w2 = wp + 2 * 9216;
    uint4* wp_fe2w2 = wp + 3 * 9216;
    uint4* wp_convw = wp + 4 * 9216;

    cudaFuncSetAttribute(conv3x3_tc,
                         cudaFuncAttributeMaxDynamicSharedMemorySize,
                         CONV_SMEM_BYTES);
    cudaFuncSetAttribute(attn_tc,
                         cudaFuncAttributeMaxDynamicSharedMemorySize, ATTN_SMEM);

    const dim3 cgrid(WW / 16, HH / 16, 4 * BB);

    pack_weights_all<<<180, 256>>>(fe1_w1, fe2_w1, fe1_w2, fe2_w2, conv_w, wp);
    pack_features_all<<<(2 * 16 * NPIX + 255) / 256, 256>>>(low1, low2, low1p, low2p);

    conv3x3_tc<<<cgrid, 256, CONV_SMEM_BYTES>>>(
        low1p, low2p, 0, wp_fe1w1, wp_fe2w1, fe1_b1, fe2_b1,
        nullptr, nullptr, tp, 1);
    conv3x3_tc<<<cgrid, 256, CONV_SMEM_BYTES>>>(
        tp, tp, NPIX * 16, wp_fe1w2, wp_fe2w2, fe1_b2, fe2_b2,
        low1, low2, ap, 2);
    conv3x3_tc<<<cgrid, 256, CONV_SMEM_BYTES>>>(
        ap, ap, NPIX * 16, wp_convw, wp_convw, conv_b, conv_b,
        nullptr, nullptr, qkp, 3);

    attn_tc<<<dim3(HH, BB), 384, ATTN_SMEM>>>(
        low1, low2, qkp, r2l1, l2r1, out, out + NT);
}

// round 10
// speedup vs baseline: 1.9321x; 1.0554x over previous
#include <cuda_runtime.h>
#include <cuda_bf16.h>

typedef unsigned int u32;
typedef unsigned long long u64;

// Problem constants
#define BB 4
#define CC 64
#define HH 192
#define WW 192
#define CS (HH*WW)            // channel stride = 36864
#define NT (BB*CC*HH*WW)      // elems per [B,C,H,W] fp32 tensor
#define NPIX (BB*HH*WW)       // pixels per tensor = 147456

// ---------------- static scratch (no runtime allocation allowed) ----------------
__device__ uint4 g_low1p[NPIX * 16];
__device__ uint4 g_low2p[NPIX * 16];
__device__ uint4 g_tp[4 * NPIX * 16];   // packed conv1 outputs, per combo
__device__ uint4 g_ap[4 * NPIX * 16];   // packed conv2 outputs, per combo
__device__ uint4 g_qkp[4 * NPIX * 16];  // packed conv3 outputs: Q1,K1,Q2,K2
__device__ uint4 g_wp[5][9216];         // prepacked weights
__device__ float g_r2l1[NT];
__device__ float g_l2r1[NT];

// ---------------- helpers ----------------
__device__ __forceinline__ void split_pack(float ev, float ov, u32 &hi, u32 &lo)
{
    __nv_bfloat16 eh = __float2bfloat16(ev);
    __nv_bfloat16 oh = __float2bfloat16(ov);
    __nv_bfloat16 el = __float2bfloat16(ev - __bfloat162float(eh));
    __nv_bfloat16 ol = __float2bfloat16(ov - __bfloat162float(oh));
    hi = (u32)__bfloat16_as_ushort(eh) | ((u32)__bfloat16_as_ushort(oh) << 16);
    lo = (u32)__bfloat16_as_ushort(el) | ((u32)__bfloat16_as_ushort(ol) << 16);
}

__device__ __forceinline__ void mma16816(float c[4],
                                         u32 a0, u32 a1, u32 a2, u32 a3,
                                         u32 b0, u32 b1)
{
    asm volatile(
        "mma.sync.aligned.m16n8k16.row.col.f32.bf16.bf16.f32 "
        "{%0,%1,%2,%3}, {%4,%5,%6,%7}, {%8,%9}, {%0,%1,%2,%3};"
        : "+f"(c[0]), "+f"(c[1]), "+f"(c[2]), "+f"(c[3])
        : "r"(a0), "r"(a1), "r"(a2), "r"(a3), "r"(b0), "r"(b1));
}

__device__ __forceinline__ void ldsm4(u32 f[4], u32 addr)
{
    asm volatile(
        "ldmatrix.sync.aligned.m8n8.x4.shared.b16 {%0,%1,%2,%3}, [%4];"
        : "=r"(f[0]), "=r"(f[1]), "=r"(f[2]), "=r"(f[3]) : "r"(addr));
}

__device__ __forceinline__ void ldsm4t(u32 f[4], u32 addr)
{
    asm volatile(
        "ldmatrix.sync.aligned.m8n8.x4.trans.shared.b16 {%0,%1,%2,%3}, [%4];"
        : "=r"(f[0]), "=r"(f[1]), "=r"(f[2]), "=r"(f[3]) : "r"(addr));
}

// =================================================================================
// Prep kernels (one launch each)
// =================================================================================
__global__ void pack_weights_all(
    const float* __restrict__ w0, const float* __restrict__ w1,
    const float* __restrict__ w2, const float* __restrict__ w3,
    const float* __restrict__ w4, uint4* __restrict__ wp)
{
    int idx = blockIdx.x * 256 + threadIdx.x;
    if (idx >= 5 * 9216) return;
    int which = idx / 9216, r = idx % 9216;
    const float* w = (which == 0) ? w0 : (which == 1) ? w1 :
                     (which == 2) ? w2 : (which == 3) ? w3 : w4;
    int tap = r >> 10, rem = r & 1023;
    int chunk = rem >> 8, rem2 = rem & 255;
    int o = rem2 >> 2, t = rem2 & 3;
    int c2a = chunk * 8 + t, c2b = c2a + 4;
    u32 h0, l0, h1, l1;
    split_pack(__ldg(&w[o * 576 + (2 * c2a) * 9 + tap]),
               __ldg(&w[o * 576 + (2 * c2a + 1) * 9 + tap]), h0, l0);
    split_pack(__ldg(&w[o * 576 + (2 * c2b) * 9 + tap]),
               __ldg(&w[o * 576 + (2 * c2b + 1) * 9 + tap]), h1, l1);
    wp[idx] = make_uint4(h0, h1, l0, l1);
}

__global__ void pack_features_all(const float* __restrict__ x1,
                                  const float* __restrict__ x2,
                                  uint4* __restrict__ xp1,
                                  uint4* __restrict__ xp2)
{
    int gi = blockIdx.x * 256 + threadIdx.x;
    if (gi >= 2 * 16 * NPIX) return;
    int tsel = gi / (16 * NPIX);
    int r = gi - tsel * 16 * NPIX;
    int j = r / NPIX;
    int p = r - j * NPIX;
    const float* x = tsel ? x2 : x1;
    uint4* xp = tsel ? xp2 : xp1;
    int b = p / (HH * WW);
    int pos = p - b * HH * WW;
    const float* src = x + (size_t)(b * 64 + 4 * j) * CS + pos;
    u32 h0, l0, h1, l1;
    split_pack(src[0], src[CS], h0, l0);
    split_pack(src[2 * CS], src[3 * CS], h1, l1);
    xp[(size_t)p * 16 + j] = make_uint4(h0, l0, h1, l1);
}

// =================================================================================
// Tensor-core conv 3x3 (stride1 pad1 C64->C64), bf16x3, NHWC halo + ldmatrix.
// NEW warp shape: 8 warps, warp = 4 image rows x 32 och (wr = wid&3 row group,
// wh = wid>>2 och half). B fragments per warp halve (each feeds 12 MMAs);
// A loaded as 6 halo rows per (ch,dx) shared across dy and the 4 output rows.
// mode 1: relu->packed; mode 2: +skip->packed; mode 3: bias only->packed.
// =================================================================================
#define CONV_SMEM_BYTES (23040*4)

__global__ void __launch_bounds__(256, 2) conv3x3_tc(
    const uint4* __restrict__ xpA, const uint4* __restrict__ xpB, int xstride_u4,
    const uint4* __restrict__ wpA, const uint4* __restrict__ wpB,
    const float* __restrict__ bsA, const float* __restrict__ bsB,
    const float* __restrict__ skA, const float* __restrict__ skB,
    uint4* __restrict__ yp, int mode)
{
    extern __shared__ u32 smc[];
    u32* Hhi = smc;
    u32* Hlo = smc + 11520;

    const int bz = blockIdx.z;
    const int combo = bz >> 2, b = bz & 3;
    const uint4* xp = ((combo & 1) ? xpB : xpA) + (size_t)combo * xstride_u4;
    const uint4* wp = (combo >> 1) ? wpB : wpA;
    const float* bias = (combo >> 1) ? bsB : bsA;
    const float* skip = (combo & 1) ? skB : skA;

    const int ty = blockIdx.y, tx = blockIdx.x;
    const int tid = threadIdx.x, wid = tid >> 5, lane = tid & 31;
    const int g = lane >> 2, t = lane & 3;
    const int wr = wid & 3, wh = wid >> 2;   // row-group / och-half

    // ---- stage NHWC halo (18x18 pixels, zero-padded at image border) ----
    const int y0 = ty * 16 - 1, x0 = tx * 16 - 1;
    for (int i = tid; i < 324 * 16; i += 256) {
        int pix = i >> 4, j = i & 15;
        int yy = pix / 18, xx = pix - yy * 18;
        int gy = y0 + yy, gx = x0 + xx;
        uint4 v = make_uint4(0u, 0u, 0u, 0u);
        if (gy >= 0 && gy < HH && gx >= 0 && gx < WW)
            v = __ldg(&xp[(size_t)((b * HH + gy) * WW + gx) * 16 + j]);
        int unitoff = (yy * 20 + xx) * 32 + (((j >> 1) ^ (xx & 7)) << 2) + ((j & 1) << 1);
        *(uint2*)&Hhi[unitoff] = make_uint2(v.x, v.z);
        *(uint2*)&Hlo[unitoff] = make_uint2(v.y, v.w);
    }
    __syncthreads();

    float acc[4][4][4];   // [mi(row)][n8l(och octet)][quad]
#pragma unroll
    for (int mi = 0; mi < 4; mi++)
#pragma unroll
        for (int n8 = 0; n8 < 4; n8++)
#pragma unroll
            for (int q = 0; q < 4; q++) acc[mi][n8][q] = 0.f;

    const int row0 = 4 * wr;
    const u32 hbase = (u32)__cvta_generic_to_shared(Hhi);
    const u32 lbase = (u32)__cvta_generic_to_shared(Hlo);
    const int m = lane & 15, half = lane >> 4;

    for (int ch = 0; ch < 4; ch++) {
#pragma unroll
        for (int dx = 0; dx < 3; dx++) {
            const int xm = dx + m;
            const int coff = (((ch * 2 + half) ^ (xm & 7)) << 4);
            const u32 a0 = (u32)((row0 * 20 + xm) * 128 + coff);
            // 6 halo rows cover 4 output rows x 3 dy via ri = mi + dy
            u32 fh[6][4], fl[6][4];
#pragma unroll
            for (int ri = 0; ri < 6; ri++) {
                ldsm4(fh[ri], hbase + a0 + ri * 2560);
                ldsm4(fl[ri], lbase + a0 + ri * 2560);
            }
#pragma unroll
            for (int dy = 0; dy < 3; dy++) {
                const uint4* wrow = wp + (((dy * 3 + dx) * 4 + ch) * 64) * 4 + t;
#pragma unroll
                for (int n8l = 0; n8l < 4; n8l++) {
                    const int n8g = wh * 4 + n8l;
                    uint4 Bv = __ldg(&wrow[(n8g * 8 + g) * 4]);
#pragma unroll
                    for (int mi = 0; mi < 4; mi++) {
                        const int ri = mi + dy;
                        mma16816(acc[mi][n8l], fh[ri][0], fh[ri][1], fh[ri][2], fh[ri][3], Bv.x, Bv.y);
                        mma16816(acc[mi][n8l], fh[ri][0], fh[ri][1], fh[ri][2], fh[ri][3], Bv.z, Bv.w);
                        mma16816(acc[mi][n8l], fl[ri][0], fl[ri][1], fl[ri][2], fl[ri][3], Bv.x, Bv.y);
                    }
                }
            }
        }
    }

    // ---- epilogue (packed NHWC out) ----
    const int gyb = ty * 16 + row0, gxb = tx * 16;
    uint2* ypc = (uint2*)(yp + (size_t)combo * (NPIX * 16));
#pragma unroll
    for (int n8l = 0; n8l < 4; n8l++) {
        const int n8g = wh * 4 + n8l;
        const int och0 = n8g * 8 + 2 * t;
        const float b0 = __ldg(&bias[och0]);
        const float b1 = __ldg(&bias[och0 + 1]);
        const int c2o = n8g * 4 + t;
#pragma unroll
        for (int mi = 0; mi < 4; mi++) {
            const int gy = gyb + mi;
#pragma unroll
            for (int hlf = 0; hlf < 2; hlf++) {
                const int px = gxb + g + hlf * 8;
                float v0 = acc[mi][n8l][hlf * 2 + 0] + b0;
                float v1 = acc[mi][n8l][hlf * 2 + 1] + b1;
                if (mode == 1) {
                    v0 = fmaxf(v0, 0.f);
                    v1 = fmaxf(v1, 0.f);
                } else if (mode == 2) {
                    const int off = ((b * 64 + och0) * HH + gy) * WW + px;
                    v0 += __ldg(&skip[off]);
                    v1 += __ldg(&skip[off + CS]);
                }
                u32 h, l;
                split_pack(v0, v1, h, l);
                ypc[(size_t)((b * HH + gy) * WW + px) * 32 + c2o] = make_uint2(h, l);
            }
        }
    }
}

// =================================================================================
// Tensor-core attention (R9 design, passing): one CTA per (b,h), 384 threads,
// 6 MMA phases with stage-2 linearity fusion.
// =================================================================================
#define SH_B   0
#define SL_B   73728
#define QSH_U  0        // u32 indices
#define QSL_U  6144
#define KH_U   12288
#define KL_U   19200
#define FH_U   36864
#define FL_U   43264
#define ATTN_SMEM 198656

__device__ __forceinline__ void stage_qk(u32* sm, const uint4* __restrict__ q,
                                         const uint4* __restrict__ k,
                                         int pixbase, int tid)
{
#pragma unroll
    for (int it = 0; it < 8; it++) {
        int i = tid + it * 384;
        int p = i >> 4, j = i & 15;
        uint4 vq = __ldg(&q[(size_t)(pixbase + p) * 16 + j]);
        uint4 vk = __ldg(&k[(size_t)(pixbase + p) * 16 + j]);
        int us = (j >> 1) ^ (p & 7);
        int qoff = p * 32 + us * 4 + (j & 1) * 2;
        *(uint2*)(sm + QSH_U + qoff) = make_uint2(vq.x, vq.z);
        *(uint2*)(sm + QSL_U + qoff) = make_uint2(vq.y, vq.w);
        int koff = p * 36 + 2 * j;
        *(uint2*)(sm + KH_U + koff) = make_uint2(vk.x, vk.z);
        *(uint2*)(sm + KL_U + koff) = make_uint2(vk.y, vk.w);
    }
}

__device__ __forceinline__ void compute_store_S(u32* sm, u32 smem_base,
                                                int wid, int lane)
{
    const int g = lane >> 2, t = lane & 3;
    const int w0 = wid * 16;
    const int tile = lane >> 3, lr = lane & 7;
    const int arow = w0 + lr + ((tile & 1) << 3);

    float acc[24][4];
#pragma unroll
    for (int n8 = 0; n8 < 24; n8++)
#pragma unroll
        for (int q = 0; q < 4; q++) acc[n8][q] = 0.f;

    const u32* kh = sm + KH_U;
    const u32* kl = sm + KL_U;

#pragma unroll
    for (int ch = 0; ch < 4; ch++) {
        const int ut = 2 * ch + (tile >> 1);
        const int us = ut ^ (arow & 7);
        const u32 qaddr = smem_base + (u32)(arow * 128 + us * 16);
        u32 ah[4], al[4];
        ldsm4(ah, qaddr);
        ldsm4(al, qaddr + 24576);
        const int kbase = ch * 8 + t;
#pragma unroll
        for (int n8 = 0; n8 < 24; n8++) {
            const int p36 = (n8 * 8 + g) * 36;
            u32 b0h = kh[p36 + kbase], b1h = kh[p36 + kbase + 4];
            u32 b0l = kl[p36 + kbase], b1l = kl[p36 + kbase + 4];
            mma16816(acc[n8], ah[0], ah[1], ah[2], ah[3], b0h, b1h);
            mma16816(acc[n8], ah[0], ah[1], ah[2], ah[3], b0l, b1l);
            mma16816(acc[n8], al[0], al[1], al[2], al[3], b0h, b1h);
        }
    }

    float m0 = -1e30f, m1 = -1e30f;
#pragma unroll
    for (int n8 = 0; n8 < 24; n8++) {
        m0 = fmaxf(m0, fmaxf(acc[n8][0], acc[n8][1]));
        m1 = fmaxf(m1, fmaxf(acc[n8][2], acc[n8][3]));
    }
    m0 = fmaxf(m0, __shfl_xor_sync(0xffffffffu, m0, 1));
    m0 = fmaxf(m0, __shfl_xor_sync(0xffffffffu, m0, 2));
    m1 = fmaxf(m1, __shfl_xor_sync(0xffffffffu, m1, 1));
    m1 = fmaxf(m1, __shfl_xor_sync(0xffffffffu, m1, 2));
    float s0 = 0.f, s1 = 0.f;
#pragma unroll
    for (int n8 = 0; n8 < 24; n8++) {
        acc[n8][0] = __expf(acc[n8][0] - m0);
        acc[n8][1] = __expf(acc[n8][1] - m0);
        acc[n8][2] = __expf(acc[n8][2] - m1);
        acc[n8][3] = __expf(acc[n8][3] - m1);
        s0 += acc[n8][0] + acc[n8][1];
        s1 += acc[n8][2] + acc[n8][3];
    }
    s0 += __shfl_xor_sync(0xffffffffu, s0, 1);
    s0 += __shfl_xor_sync(0xffffffffu, s0, 2);
    s1 += __shfl_xor_sync(0xffffffffu, s1, 1);
    s1 += __shfl_xor_sync(0xffffffffu, s1, 2);
    const float inv0 = 1.0f / s0, inv1 = 1.0f / s1;

    __syncthreads();   // all warps done reading Qs/Ks before S overwrites them

    u32* shp = sm;                    // Sh as u32, row stride 96
    u32* slp = sm + SL_B / 4;
    const int rg = w0 + g;
#pragma unroll
    for (int n8 = 0; n8 < 24; n8++) {
        const int us = (n8 & 24) | ((n8 & 7) ^ (rg & 7));
        const int off = us * 4 + t;
        u32 h, l;
        split_pack(acc[n8][0] * inv0, acc[n8][1] * inv0, h, l);
        shp[rg * 96 + off] = h;
        slp[rg * 96 + off] = l;
        split_pack(acc[n8][2] * inv1, acc[n8][3] * inv1, h, l);
        shp[(rg + 8) * 96 + off] = h;
        slp[(rg + 8) * 96 + off] = l;
    }
}

__device__ __forceinline__ void load_F(u32* sm, const float* __restrict__ src,
                                       int rb, int tid)
{
#pragma unroll
    for (int it = 0; it < 8; it++) {
        int i = tid + it * 384;
        int c = i / 48, q = i - c * 48;
        float4 f = *(const float4*)(src + rb + c * CS + q * 4);
        u32 h0, l0, h1, l1;
        split_pack(f.x, f.y, h0, l0);
        split_pack(f.z, f.w, h1, l1);
        *(uint2*)(sm + FH_U + c * 100 + 2 * q) = make_uint2(h0, h1);
        *(uint2*)(sm + FL_U + c * 100 + 2 * q) = make_uint2(l0, l1);
    }
}

__device__ __forceinline__ void load_F2(u32* sm, const float* __restrict__ srcA,
                                        const float* __restrict__ srcB,
                                        int rb, int tid)
{
#pragma unroll
    for (int it = 0; it < 8; it++) {
        int i = tid + it * 384;
        int c = i / 48, q = i - c * 48;
        float4 fa = *(const float4*)(srcA + rb + c * CS + q * 4);
        float4 fb = *(const float4*)(srcB + rb + c * CS + q * 4);
        float4 f = make_float4(fa.x + fb.x, fa.y + fb.y, fa.z + fb.z, fa.w + fb.w);
        u32 h0, l0, h1, l1;
        split_pack(f.x, f.y, h0, l0);
        split_pack(f.z, f.w, h1, l1);
        *(uint2*)(sm + FH_U + c * 100 + 2 * q) = make_uint2(h0, h1);
        *(uint2*)(sm + FL_U + c * 100 + 2 * q) = make_uint2(l0, l1);
    }
}

template <bool TR>
__device__ __forceinline__ void apply_tc(u32* sm, u32 smem_base,
                                         int wid, int lane, float acc[8][4])
{
    const int g = lane >> 2, t = lane & 3;
    const int w0 = wid * 16;
    const int tile = lane >> 3, lr = lane & 7;
    const u32* fh = sm + FH_U;
    const u32* fl = sm + FL_U;

#pragma unroll
    for (int n8 = 0; n8 < 8; n8++)
#pragma unroll
        for (int q = 0; q < 4; q++) acc[n8][q] = 0.f;

#pragma unroll
    for (int k = 0; k < 12; k++) {
        u32 ah[4], al[4];
        if (!TR) {
            const int row = w0 + lr + ((tile & 1) << 3);
            const int ut = 2 * k + (tile >> 1);
            const int us = (ut & 24) | ((ut & 7) ^ (row & 7));
            const u32 addr = smem_base + (u32)(row * 384 + us * 16);
            ldsm4(ah, addr);
            ldsm4(al, addr + 73728);
        } else {
            const int srow = k * 16 + lr + ((tile >> 1) << 3);
            const int cu = 2 * wid + (tile & 1);
            const int us = (cu & 24) | ((cu & 7) ^ (srow & 7));
            const u32 addr = smem_base + (u32)(srow * 384 + us * 16);
            ldsm4t(ah, addr);
            ldsm4t(al, addr + 73728);
        }
        const int fb = 8 * k + t;
#pragma unroll
        for (int n8 = 0; n8 < 8; n8++) {
            const int c100 = (n8 * 8 + g) * 100;
            u32 b0h = fh[c100 + fb], b1h = fh[c100 + fb + 4];
            u32 b0l = fl[c100 + fb], b1l = fl[c100 + fb + 4];
            mma16816(acc[n8], ah[0], ah[1], ah[2], ah[3], b0h, b1h);
            mma16816(acc[n8], ah[0], ah[1], ah[2], ah[3], b0l, b1l);
            mma16816(acc[n8], al[0], al[1], al[2], al[3], b0h, b1h);
        }
    }
}

__device__ __forceinline__ void emit_init2(float* dst, float* scratch,
                                           const float* base, const float acc[8][4],
                                           int rb, int wid, int lane)
{
    const int g = lane >> 2, t = lane & 3, w0 = wid * 16;
#pragma unroll
    for (int n8 = 0; n8 < 8; n8++)
#pragma unroll
        for (int q = 0; q < 4; q++) {
            const int c = n8 * 8 + 2 * t + (q & 1);
            const int w = w0 + g + ((q >> 1) << 3);
            const int off = rb + c * CS + w;
            const float v = acc[n8][q];
            scratch[off] = v;
            dst[off] = base[off] + v;
        }
}

__device__ __forceinline__ void emit_add2(float* dst, const float acc[8][4],
                                          int rb, int wid, int lane)
{
    const int g = lane >> 2, t = lane & 3, w0 = wid * 16;
#pragma unroll
    for (int n8 = 0; n8 < 8; n8++)
#pragma unroll
        for (int q = 0; q < 4; q++) {
            const int c = n8 * 8 + 2 * t + (q & 1);
            const int w = w0 + g + ((q >> 1) << 3);
            dst[rb + c * CS + w] += acc[n8][q];
        }
}

__global__ void __launch_bounds__(384, 1) attn_tc(
    const float* __restrict__ low1, const float* __restrict__ low2,
    const uint4* __restrict__ qkp,
    float* __restrict__ r2l1s, float* __restrict__ l2r1s,
    float* __restrict__ outL, float* __restrict__ outR)
{
    extern __shared__ u32 sm[];
    const int h = blockIdx.x, b = blockIdx.y;
    const int tid = threadIdx.x, wid = tid >> 5, lane = tid & 31;
    const int rb = b * 64 * CS + h * WW;
    const int pixbase = (b * HH + h) * WW;
    const u32 smem_base = (u32)__cvta_generic_to_shared(sm);
    float acc[8][4];

    // ---- stage 1: S1 = softmax(Q1^T K1) ----
    stage_qk(sm, qkp + 0, qkp + (size_t)1 * NPIX * 16, pixbase, tid);
    __syncthreads();
    compute_store_S(sm, smem_base, wid, lane);
    __syncthreads();

    load_F(sm, low2, rb, tid); __syncthreads();
    apply_tc<false>(sm, smem_base, wid, lane, acc);
    emit_init2(outL, r2l1s, low1, acc, rb, wid, lane);
    __syncthreads();

    load_F(sm, low1, rb, tid); __syncthreads();
    apply_tc<true>(sm, smem_base, wid, lane, acc);
    emit_init2(outR, l2r1s, low2, acc, rb, wid, lane);
    __syncthreads();

    // ---- stage 2: S2 = softmax(Q2^T K2) ----
    stage_qk(sm, qkp + (size_t)2 * NPIX * 16, qkp + (size_t)3 * NPIX * 16,
             pixbase, tid);
    __syncthreads();
    compute_store_S(sm, smem_base, wid, lane);
    __syncthreads();

    // outL += S2 @ (low2 + l2r1)
    load_F2(sm, low2, l2r1s, rb, tid); __syncthreads();
    apply_tc<false>(sm, smem_base, wid, lane, acc);
    emit_add2(outL, acc, rb, wid, lane);
    __syncthreads();

    // outR += S2^T @ (low1 + r2l1)
    load_F2(sm, low1, r2l1s, rb, tid); __syncthreads();
    apply_tc<true>(sm, smem_base, wid, lane, acc);
    emit_add2(outR, acc, rb, wid, lane);
}

// =================================================================================
extern "C" void kernel_launch(void* const* d_in, const int* in_sizes, int n_in,
                              void* d_out, int out_size)
{
    const float* low1   = (const float*)d_in[0];
    const float* low2   = (const float*)d_in[1];
    const float* fe1_w1 = (const float*)d_in[2];
    const float* fe1_b1 = (const float*)d_in[3];
    const float* fe1_w2 = (const float*)d_in[4];
    const float* fe1_b2 = (const float*)d_in[5];
    const float* fe2_w1 = (const float*)d_in[6];
    const float* fe2_b1 = (const float*)d_in[7];
    const float* fe2_w2 = (const float*)d_in[8];
    const float* fe2_b2 = (const float*)d_in[9];
    const float* conv_w = (const float*)d_in[10];
    const float* conv_b = (const float*)d_in[11];
    float* out = (float*)d_out;

    uint4 *low1p, *low2p, *tp, *ap, *qkp, *wp;
    float *r2l1, *l2r1;
    cudaGetSymbolAddress((void**)&low1p, g_low1p);
    cudaGetSymbolAddress((void**)&low2p, g_low2p);
    cudaGetSymbolAddress((void**)&tp,    g_tp);
    cudaGetSymbolAddress((void**)&ap,    g_ap);
    cudaGetSymbolAddress((void**)&qkp,   g_qkp);
    cudaGetSymbolAddress((void**)&wp,    g_wp);
    cudaGetSymbolAddress((void**)&r2l1,  g_r2l1);
    cudaGetSymbolAddress((void**)&l2r1,  g_l2r1);

    uint4* wp_fe1w1 = wp + 0 * 9216;
    uint4* wp_fe2w1 = wp + 1 * 9216;
    uint4* wp_fe1w2 = wp + 2 * 9216;
    uint4* wp_fe2w2 = wp + 3 * 9216;
    uint4* wp_convw = wp + 4 * 9216;

    cudaFuncSetAttribute(conv3x3_tc,
                         cudaFuncAttributeMaxDynamicSharedMemorySize,
                         CONV_SMEM_BYTES);
    cudaFuncSetAttribute(attn_tc,
                         cudaFuncAttributeMaxDynamicSharedMemorySize, ATTN_SMEM);

    const dim3 cgrid(WW / 16, HH / 16, 4 * BB);

    pack_weights_all<<<180, 256>>>(fe1_w1, fe2_w1, fe1_w2, fe2_w2, conv_w, wp);
    pack_features_all<<<(2 * 16 * NPIX + 255) / 256, 256>>>(low1, low2, low1p, low2p);

    conv3x3_tc<<<cgrid, 256, CONV_SMEM_BYTES>>>(
        low1p, low2p, 0, wp_fe1w1, wp_fe2w1, fe1_b1, fe2_b1,
        nullptr, nullptr, tp, 1);
    conv3x3_tc<<<cgrid, 256, CONV_SMEM_BYTES>>>(
        tp, tp, NPIX * 16, wp_fe1w2, wp_fe2w2, fe1_b2, fe2_b2,
        low1, low2, ap, 2);
    conv3x3_tc<<<cgrid, 256, CONV_SMEM_BYTES>>>(
        ap, ap, NPIX * 16, wp_convw, wp_convw, conv_b, conv_b,
        nullptr, nullptr, qkp, 3);

    attn_tc<<<dim3(HH, BB), 384, ATTN_SMEM>>>(
        low1, low2, qkp, r2l1, l2r1, out, out + NT);
}